// round 6
// baseline (speedup 1.0000x reference)
#include <cuda_runtime.h>
#include <cstdint>
#include <math.h>

#define T_TOK 1024
#define H_DIM 2048
#define E_NUM 64
#define I_DIM 512
#define IS_DIM 1024
#define TOPK 8
#define CAP 256

// GEMM tiling
#define BK 32
#define ROWB 144              // padded row stride in bytes (36 floats)
#define A_BYTES (128 * ROWB)  // 18432
#define STG (A_BYTES + 128 * ROWB)   // stage = A + B(128 rows worth) = 36864
#define SM_MM (2 * STG)              // 73728

// ---------------- scratch (static device globals; no allocs) ----------------
__device__ int   d_topk_idx[T_TOK * TOPK];
__device__ float d_topk_w[T_TOK * TOPK];
__device__ float d_sgate[T_TOK];
__device__ int   d_cnt[E_NUM];
__device__ int   d_toklist[E_NUM * CAP];
__device__ int   d_pos[T_TOK * TOPK];
__device__ float d_gbuf[(size_t)E_NUM * CAP * I_DIM];
__device__ float d_yb[(size_t)E_NUM * CAP * H_DIM];
__device__ float d_s1[(size_t)T_TOK * IS_DIM];
__device__ float d_s2[(size_t)T_TOK * H_DIM];

// ---------------- helpers ----------------
__device__ __forceinline__ unsigned tf32r(float x) {
    unsigned r;
    asm("cvt.rna.tf32.f32 %0, %1;" : "=r"(r) : "f"(x));
    return r;
}
__device__ __forceinline__ uint32_t smem_u32(const void* p) {
    return (uint32_t)__cvta_generic_to_shared(p);
}
#define LDSM4(r, addr) \
    asm volatile("ldmatrix.sync.aligned.m8n8.x4.shared.b16 {%0,%1,%2,%3}, [%4];" \
        : "=r"((r)[0]), "=r"((r)[1]), "=r"((r)[2]), "=r"((r)[3]) : "r"(addr))

__device__ __forceinline__ void mma8(float* c, const uint32_t* a, uint32_t b0, uint32_t b1) {
    asm volatile(
        "mma.sync.aligned.m16n8k8.row.col.f32.tf32.tf32.f32 "
        "{%0,%1,%2,%3}, {%4,%5,%6,%7}, {%8,%9}, {%0,%1,%2,%3};"
        : "+f"(c[0]), "+f"(c[1]), "+f"(c[2]), "+f"(c[3])
        : "r"(a[0]), "r"(a[1]), "r"(a[2]), "r"(a[3]), "r"(b0), "r"(b1));
}

// ---------------- router ----------------
__global__ void router_kernel(const float* __restrict__ x,
                              const float* __restrict__ gw,
                              const float* __restrict__ wsg) {
    int t = blockIdx.x;
    __shared__ float xs[H_DIM];
    __shared__ float logits[E_NUM + 1];
    const float4* xr = (const float4*)(x + (size_t)t * H_DIM);
    for (int i = threadIdx.x; i < H_DIM / 4; i += blockDim.x)
        ((float4*)xs)[i] = xr[i];
    __syncthreads();
    int warp = threadIdx.x >> 5, lane = threadIdx.x & 31;
    for (int u = warp; u < E_NUM + 1; u += 8) {
        const float4* wrow = (const float4*)((u < E_NUM) ? (gw + (size_t)u * H_DIM) : wsg);
        float s = 0.f;
        for (int i = lane; i < H_DIM / 4; i += 32) {
            float4 a = ((const float4*)xs)[i];
            float4 b = wrow[i];
            s += a.x * b.x + a.y * b.y + a.z * b.z + a.w * b.w;
        }
        #pragma unroll
        for (int o = 16; o; o >>= 1) s += __shfl_xor_sync(0xffffffffu, s, o);
        if (lane == 0) logits[u] = s;
    }
    __syncthreads();
    if (threadIdx.x == 0) {
        unsigned long long used = 0ull;
        float vals[TOPK]; int idx[TOPK];
        for (int k = 0; k < TOPK; k++) {
            float best = -INFINITY; int bi = 0;
            for (int e = 0; e < E_NUM; e++)
                if (!((used >> e) & 1ull) && logits[e] > best) { best = logits[e]; bi = e; }
            used |= 1ull << bi; vals[k] = best; idx[k] = bi;
        }
        float m = vals[0], sum = 0.f, w[TOPK];
        for (int k = 0; k < TOPK; k++) { w[k] = expf(vals[k] - m); sum += w[k]; }
        float inv = 1.f / sum;
        for (int k = 0; k < TOPK; k++) {
            d_topk_w[t * TOPK + k]  = w[k] * inv;
            d_topk_idx[t * TOPK + k] = idx[k];
        }
        d_sgate[t] = logits[E_NUM];
    }
}

// ------- dispatch: stable rank within expert -------
__global__ void dispatch_kernel() {
    int e = blockIdx.x;
    __shared__ int warp_sums[8];
    __shared__ int base_s;
    if (threadIdx.x == 0) base_s = 0;
    int lane = threadIdx.x & 31, warp = threadIdx.x >> 5;
    for (int c = 0; c < T_TOK * TOPK; c += 256) {
        __syncthreads();
        int i = c + threadIdx.x;
        bool m = (d_topk_idx[i] == e);
        unsigned mask = __ballot_sync(0xffffffffu, m);
        if (lane == 0) warp_sums[warp] = __popc(mask);
        __syncthreads();
        int off = 0, total = 0;
        #pragma unroll
        for (int w = 0; w < 8; w++) { int v = warp_sums[w]; total += v; if (w < warp) off += v; }
        if (m) {
            int pos = base_s + off + __popc(mask & ((1u << lane) - 1u));
            d_pos[i] = pos;
            if (pos < CAP) d_toklist[e * CAP + pos] = i >> 3;
        }
        __syncthreads();
        if (threadIdx.x == 0) base_s += total;
    }
    __syncthreads();
    if (threadIdx.x == 0) d_cnt[e] = min(base_s, CAP);
}

// ========== dual GEMM + SwiGLU: Out = silu(A@B1) * (A@B3) ==========
// 512 threads, 16 warps (4m x 4n). Block 128x64 (x2 mats). Warp tile 32x16/mat.
// A smem [m][k] K-major tf32, B smem [n][k] (producer-transposed) tf32, 144B rows.
__global__ void __launch_bounds__(512, 1)
mm_dual(const float* __restrict__ A, int lda, size_t strideA,
        const int* __restrict__ gather, const int* __restrict__ cnt,
        int mfull, int mtiles,
        const float* __restrict__ B1g, const float* __restrict__ B3g,
        int ldb, size_t strideB,
        float* __restrict__ Out, int ldo, size_t strideOut, int K) {
    extern __shared__ __align__(16) unsigned char smraw[];
    uint32_t smb = smem_u32(smraw);

    int e = blockIdx.x / mtiles, mt = blockIdx.x - e * mtiles;
    int noff = blockIdx.y * 64;
    int nrows = cnt ? cnt[e] - mt * 128 : mfull - mt * 128;
    if (nrows <= 0) return;
    int valid = min(128, nrows);

    int tid = threadIdx.x, wid = tid >> 5, lane = tid & 31;
    int wm = wid & 3, wn = wid >> 2;
    int g = lane >> 2, t4 = lane & 3;

    // producer addressing: A 2 f4/thread; B 1 f4 per mat per thread
    const float* ap[2]; uint32_t asts[2];
    #pragma unroll
    for (int jj = 0; jj < 2; jj++) {
        int idx = tid + 512 * jj;
        int r = idx >> 3, c4 = idx & 7;
        int rr = min(r, valid - 1);
        long gr = gather ? (long)gather[e * CAP + mt * 128 + rr] : (long)(mt * 128 + rr);
        ap[jj] = A + (size_t)e * strideA + (size_t)gr * lda + c4 * 4;
        asts[jj] = (uint32_t)(r * ROWB + c4 * 16);
    }
    const float *b1p, *b3p; uint32_t bsts;
    {
        int kq = tid & 31, n4 = (tid >> 5) * 4;
        size_t go = (size_t)e * strideB + (size_t)kq * ldb + noff + n4;
        b1p = B1g + go; b3p = B3g + go;
        bsts = (uint32_t)(n4 * ROWB + kq * 4);
    }

    // ldmatrix lane offsets
    uint32_t aoff[2];
    #pragma unroll
    for (int mf = 0; mf < 2; mf++) {
        int row = wm * 32 + mf * 16 + ((lane >> 3) & 1) * 8 + (lane & 7);
        aoff[mf] = (uint32_t)(row * ROWB + (lane >> 4) * 16);
    }
    uint32_t boff;
    {
        int row = wn * 16 + (lane >> 4) * 8 + (lane & 7);
        boff = (uint32_t)(row * ROWB + ((lane >> 3) & 1) * 16);
    }

    float c1[2][2][4], c3[2][2][4];
    #pragma unroll
    for (int a = 0; a < 2; a++)
        #pragma unroll
        for (int b = 0; b < 2; b++)
            #pragma unroll
            for (int r = 0; r < 4; r++) { c1[a][b][r] = 0.f; c3[a][b][r] = 0.f; }

    float4 ra[2], rb1, rb3;
    auto ldg_all = [&]() {
        #pragma unroll
        for (int jj = 0; jj < 2; jj++) { ra[jj] = *(const float4*)ap[jj]; ap[jj] += BK; }
        rb1 = *(const float4*)b1p; b1p += (size_t)BK * ldb;
        rb3 = *(const float4*)b3p; b3p += (size_t)BK * ldb;
    };
    auto sts_all = [&](int s) {
        uint32_t ab = smb + s * STG;
        #pragma unroll
        for (int jj = 0; jj < 2; jj++) {
            asm volatile("st.shared.v4.b32 [%0], {%1,%2,%3,%4};"
                :: "r"(ab + asts[jj]),
                   "r"(tf32r(ra[jj].x)), "r"(tf32r(ra[jj].y)),
                   "r"(tf32r(ra[jj].z)), "r"(tf32r(ra[jj].w)));
        }
        uint32_t b1a = ab + A_BYTES + bsts;
        asm volatile("st.shared.b32 [%0], %1;" :: "r"(b1a),            "r"(tf32r(rb1.x)));
        asm volatile("st.shared.b32 [%0], %1;" :: "r"(b1a + ROWB),     "r"(tf32r(rb1.y)));
        asm volatile("st.shared.b32 [%0], %1;" :: "r"(b1a + 2 * ROWB), "r"(tf32r(rb1.z)));
        asm volatile("st.shared.b32 [%0], %1;" :: "r"(b1a + 3 * ROWB), "r"(tf32r(rb1.w)));
        uint32_t b3a = b1a + 64 * ROWB;
        asm volatile("st.shared.b32 [%0], %1;" :: "r"(b3a),            "r"(tf32r(rb3.x)));
        asm volatile("st.shared.b32 [%0], %1;" :: "r"(b3a + ROWB),     "r"(tf32r(rb3.y)));
        asm volatile("st.shared.b32 [%0], %1;" :: "r"(b3a + 2 * ROWB), "r"(tf32r(rb3.z)));
        asm volatile("st.shared.b32 [%0], %1;" :: "r"(b3a + 3 * ROWB), "r"(tf32r(rb3.w)));
    };

    int nk = K / BK;
    ldg_all();
    for (int i = 0; i < nk; i++) {
        int s = i & 1;
        sts_all(s);
        __syncthreads();
        if (i + 1 < nk) ldg_all();
        uint32_t ab = smb + s * STG;
        uint32_t bb = ab + A_BYTES;
        #pragma unroll
        for (int kk = 0; kk < 4; kk++) {
            uint32_t af[2][4], bf1[4], bf3[4];
            LDSM4(af[0], ab + aoff[0] + kk * 32);
            LDSM4(af[1], ab + aoff[1] + kk * 32);
            LDSM4(bf1, bb + boff + kk * 32);
            LDSM4(bf3, bb + 64 * ROWB + boff + kk * 32);
            #pragma unroll
            for (int mf = 0; mf < 2; mf++)
                #pragma unroll
                for (int nf = 0; nf < 2; nf++) {
                    mma8(c1[mf][nf], af[mf], bf1[nf * 2], bf1[nf * 2 + 1]);
                    mma8(c3[mf][nf], af[mf], bf3[nf * 2], bf3[nf * 2 + 1]);
                }
        }
        __syncthreads();
    }

    float* outp = Out + (size_t)e * strideOut + (size_t)(mt * 128) * ldo + noff;
    #pragma unroll
    for (int mf = 0; mf < 2; mf++)
        #pragma unroll
        for (int nf = 0; nf < 2; nf++) {
            int r0 = wm * 32 + mf * 16 + g;
            int cc = wn * 16 + nf * 8 + t4 * 2;
            #pragma unroll
            for (int h = 0; h < 2; h++) {
                int r = r0 + h * 8;
                if (r < valid) {
                    float v1a = c1[mf][nf][h * 2 + 0], v3a = c3[mf][nf][h * 2 + 0];
                    float v1b = c1[mf][nf][h * 2 + 1], v3b = c3[mf][nf][h * 2 + 1];
                    float ga = (v1a / (1.f + expf(-v1a))) * v3a;
                    float gb = (v1b / (1.f + expf(-v1b))) * v3b;
                    *(float2*)(outp + (size_t)r * ldo + cc) = make_float2(ga, gb);
                }
            }
        }
}

// ========== single GEMM: Out = A @ B ==========
// 512 threads, 16 warps (4m x 4n). Block 128x128. Warp tile 32x32.
__global__ void __launch_bounds__(512, 1)
mm_single(const float* __restrict__ A, int lda, size_t strideA,
          const int* __restrict__ cnt, int mfull, int mtiles,
          const float* __restrict__ Bg, int ldb, size_t strideB,
          float* __restrict__ Out, int ldo, size_t strideOut, int K) {
    extern __shared__ __align__(16) unsigned char smraw[];
    uint32_t smb = smem_u32(smraw);

    int e = blockIdx.x / mtiles, mt = blockIdx.x - e * mtiles;
    int noff = blockIdx.y * 128;
    int nrows = cnt ? cnt[e] - mt * 128 : mfull - mt * 128;
    if (nrows <= 0) return;
    int valid = min(128, nrows);

    int tid = threadIdx.x, wid = tid >> 5, lane = tid & 31;
    int wm = wid & 3, wn = wid >> 2;
    int g = lane >> 2, t4 = lane & 3;

    const float* ap[2]; uint32_t asts[2];
    #pragma unroll
    for (int jj = 0; jj < 2; jj++) {
        int idx = tid + 512 * jj;
        int r = idx >> 3, c4 = idx & 7;
        ap[jj] = A + (size_t)e * strideA + (size_t)(mt * 128 + r) * lda + c4 * 4;
        asts[jj] = (uint32_t)(r * ROWB + c4 * 16);
    }
    const float* bp[2]; uint32_t bsts[2];
    #pragma unroll
    for (int jj = 0; jj < 2; jj++) {
        int idx = tid + 512 * jj;
        int kq = idx & 31, n4 = (idx >> 5) * 4;
        bp[jj] = Bg + (size_t)e * strideB + (size_t)kq * ldb + noff + n4;
        bsts[jj] = (uint32_t)(n4 * ROWB + kq * 4);
    }

    uint32_t aoff[2];
    #pragma unroll
    for (int mf = 0; mf < 2; mf++) {
        int row = wm * 32 + mf * 16 + ((lane >> 3) & 1) * 8 + (lane & 7);
        aoff[mf] = (uint32_t)(row * ROWB + (lane >> 4) * 16);
    }
    uint32_t boff[2];
    #pragma unroll
    for (int gp = 0; gp < 2; gp++) {
        int row = wn * 32 + gp * 16 + (lane >> 4) * 8 + (lane & 7);
        boff[gp] = (uint32_t)(row * ROWB + ((lane >> 3) & 1) * 16);
    }

    float c[2][4][4];
    #pragma unroll
    for (int a = 0; a < 2; a++)
        #pragma unroll
        for (int b = 0; b < 4; b++)
            #pragma unroll
            for (int r = 0; r < 4; r++) c[a][b][r] = 0.f;

    float4 ra[2], rb[2];
    auto ldg_all = [&]() {
        #pragma unroll
        for (int jj = 0; jj < 2; jj++) { ra[jj] = *(const float4*)ap[jj]; ap[jj] += BK; }
        #pragma unroll
        for (int jj = 0; jj < 2; jj++) { rb[jj] = *(const float4*)bp[jj]; bp[jj] += (size_t)BK * ldb; }
    };
    auto sts_all = [&](int s) {
        uint32_t ab = smb + s * STG;
        #pragma unroll
        for (int jj = 0; jj < 2; jj++) {
            asm volatile("st.shared.v4.b32 [%0], {%1,%2,%3,%4};"
                :: "r"(ab + asts[jj]),
                   "r"(tf32r(ra[jj].x)), "r"(tf32r(ra[jj].y)),
                   "r"(tf32r(ra[jj].z)), "r"(tf32r(ra[jj].w)));
        }
        #pragma unroll
        for (int jj = 0; jj < 2; jj++) {
            uint32_t ba = ab + A_BYTES + bsts[jj];
            asm volatile("st.shared.b32 [%0], %1;" :: "r"(ba),            "r"(tf32r(rb[jj].x)));
            asm volatile("st.shared.b32 [%0], %1;" :: "r"(ba + ROWB),     "r"(tf32r(rb[jj].y)));
            asm volatile("st.shared.b32 [%0], %1;" :: "r"(ba + 2 * ROWB), "r"(tf32r(rb[jj].z)));
            asm volatile("st.shared.b32 [%0], %1;" :: "r"(ba + 3 * ROWB), "r"(tf32r(rb[jj].w)));
        }
    };

    int nk = K / BK;
    ldg_all();
    for (int i = 0; i < nk; i++) {
        int s = i & 1;
        sts_all(s);
        __syncthreads();
        if (i + 1 < nk) ldg_all();
        uint32_t ab = smb + s * STG;
        uint32_t bb = ab + A_BYTES;
        #pragma unroll
        for (int kk = 0; kk < 4; kk++) {
            uint32_t af[2][4], bf[2][4];
            LDSM4(af[0], ab + aoff[0] + kk * 32);
            LDSM4(af[1], ab + aoff[1] + kk * 32);
            LDSM4(bf[0], bb + boff[0] + kk * 32);
            LDSM4(bf[1], bb + boff[1] + kk * 32);
            #pragma unroll
            for (int mf = 0; mf < 2; mf++)
                #pragma unroll
                for (int gp = 0; gp < 2; gp++)
                    #pragma unroll
                    for (int nf = 0; nf < 2; nf++)
                        mma8(c[mf][gp * 2 + nf], af[mf], bf[gp][nf * 2], bf[gp][nf * 2 + 1]);
        }
        __syncthreads();
    }

    float* outp = Out + (size_t)e * strideOut + (size_t)(mt * 128) * ldo + noff;
    #pragma unroll
    for (int mf = 0; mf < 2; mf++)
        #pragma unroll
        for (int nf = 0; nf < 4; nf++) {
            int r0 = wm * 32 + mf * 16 + g;
            int cc = wn * 32 + nf * 8 + t4 * 2;
            #pragma unroll
            for (int h = 0; h < 2; h++) {
                int r = r0 + h * 8;
                if (r < valid)
                    *(float2*)(outp + (size_t)r * ldo + cc) =
                        make_float2(c[mf][nf][h * 2 + 0], c[mf][nf][h * 2 + 1]);
            }
        }
}

// ---------------- combine: routed + sigmoid-gated shared ----------------
__global__ void combine_kernel(float* __restrict__ out) {
    int t = blockIdx.x;
    __shared__ int rows[TOPK];
    __shared__ float ws[TOPK];
    if (threadIdx.x < TOPK) {
        int k = threadIdx.x;
        int ee = d_topk_idx[t * TOPK + k];
        int p  = d_pos[t * TOPK + k];
        rows[k] = (p < CAP) ? (ee * CAP + p) : -1;
        ws[k] = d_topk_w[t * TOPK + k];
    }
    __syncthreads();
    float sg = 1.f / (1.f + expf(-d_sgate[t]));
    #pragma unroll
    for (int j = 0; j < 2; j++) {
        int h = threadIdx.x * 4 + j * 1024;
        float4 acc = *(const float4*)(d_s2 + (size_t)t * H_DIM + h);
        acc.x *= sg; acc.y *= sg; acc.z *= sg; acc.w *= sg;
        #pragma unroll
        for (int k = 0; k < TOPK; k++) {
            int r = rows[k];
            if (r >= 0) {
                float w = ws[k];
                float4 y = *(const float4*)(d_yb + (size_t)r * H_DIM + h);
                acc.x += w * y.x; acc.y += w * y.y; acc.z += w * y.z; acc.w += w * y.w;
            }
        }
        *(float4*)(out + (size_t)t * H_DIM + h) = acc;
    }
}

// ---------------- launch ----------------
extern "C" void kernel_launch(void* const* d_in, const int* in_sizes, int n_in,
                              void* d_out, int out_size) {
    (void)in_sizes; (void)n_in; (void)out_size;
    const float* x   = (const float*)d_in[0];
    const float* gw  = (const float*)d_in[1];
    const float* w1  = (const float*)d_in[2];
    const float* w3  = (const float*)d_in[3];
    const float* w2  = (const float*)d_in[4];
    const float* ws1 = (const float*)d_in[5];
    const float* ws3 = (const float*)d_in[6];
    const float* ws2 = (const float*)d_in[7];
    const float* wsg = (const float*)d_in[8];
    float* out = (float*)d_out;

    cudaFuncSetAttribute(mm_dual,   cudaFuncAttributeMaxDynamicSharedMemorySize, SM_MM);
    cudaFuncSetAttribute(mm_single, cudaFuncAttributeMaxDynamicSharedMemorySize, SM_MM);

    float *gbuf, *yb, *s1, *s2;
    int *cnt, *toklist;
    cudaGetSymbolAddress((void**)&gbuf, d_gbuf);
    cudaGetSymbolAddress((void**)&yb, d_yb);
    cudaGetSymbolAddress((void**)&s1, d_s1);
    cudaGetSymbolAddress((void**)&s2, d_s2);
    cudaGetSymbolAddress((void**)&cnt, d_cnt);
    cudaGetSymbolAddress((void**)&toklist, d_toklist);

    router_kernel<<<T_TOK, 256>>>(x, gw, wsg);
    dispatch_kernel<<<E_NUM, 256>>>();

    // experts: G = silu(X@w1) * (X@w3)   [gathered rows]
    mm_dual<<<dim3(E_NUM * 2, I_DIM / 64), 512, SM_MM>>>(
        x, H_DIM, 0, toklist, cnt, 0, 2,
        w1, w3, I_DIM, (size_t)H_DIM * I_DIM,
        gbuf, I_DIM, (size_t)CAP * I_DIM, H_DIM);

    // shared: S1 = silu(X@ws1) * (X@ws3)
    mm_dual<<<dim3(8, IS_DIM / 64), 512, SM_MM>>>(
        x, H_DIM, 0, nullptr, nullptr, T_TOK, 8,
        ws1, ws3, IS_DIM, 0,
        s1, IS_DIM, 0, H_DIM);

    // experts: Y = G @ w2
    mm_single<<<dim3(E_NUM * 2, H_DIM / 128), 512, SM_MM>>>(
        gbuf, I_DIM, (size_t)CAP * I_DIM, cnt, 0, 2,
        w2, H_DIM, (size_t)I_DIM * H_DIM,
        yb, H_DIM, (size_t)CAP * H_DIM, I_DIM);

    // shared: S2 = S1 @ ws2
    mm_single<<<dim3(8, H_DIM / 128), 512, SM_MM>>>(
        s1, IS_DIM, 0, nullptr, T_TOK, 8,
        ws2, H_DIM, 0,
        s2, H_DIM, 0, IS_DIM);

    combine_kernel<<<T_TOK, 256>>>(out);
}

// round 7
// speedup vs baseline: 1.2071x; 1.2071x over previous
#include <cuda_runtime.h>
#include <cstdint>
#include <math.h>

#define T_TOK 1024
#define H_DIM 2048
#define E_NUM 64
#define I_DIM 512
#define IS_DIM 1024
#define TOPK 8
#define CAP 256

// GEMM tiling
#define BK 32
#define ROWB 144                     // padded row stride in bytes (36 floats)
#define A_BYTES (128 * ROWB)         // 18432
#define STG (A_BYTES + 128 * ROWB)   // stage = A(128 rows) + B(128 n-rows) = 36864
#define SM_MM (2 * STG)              // 73728

// ---------------- scratch (static device globals; no allocs) ----------------
__device__ int   d_topk_idx[T_TOK * TOPK];
__device__ float d_topk_w[T_TOK * TOPK];
__device__ float d_sgate[T_TOK];
__device__ int   d_cnt[E_NUM];
__device__ int   d_toklist[E_NUM * CAP];
__device__ int   d_pos[T_TOK * TOPK];
__device__ float d_gbuf[(size_t)E_NUM * CAP * I_DIM];
__device__ float d_yb[(size_t)E_NUM * CAP * H_DIM];
__device__ float d_s1[(size_t)T_TOK * IS_DIM];
__device__ float d_s2[(size_t)T_TOK * H_DIM];

// ---------------- helpers ----------------
__device__ __forceinline__ unsigned tf32r(float x) {
    unsigned r;
    asm("cvt.rna.tf32.f32 %0, %1;" : "=r"(r) : "f"(x));
    return r;
}
__device__ __forceinline__ unsigned tf32b(unsigned bits) {
    unsigned r;
    asm("cvt.rna.tf32.f32 %0, %1;" : "=r"(r) : "f"(__uint_as_float(bits)));
    return r;
}
__device__ __forceinline__ uint32_t smem_u32(const void* p) {
    return (uint32_t)__cvta_generic_to_shared(p);
}
__device__ __forceinline__ void cp16(uint32_t smem_dst, const void* gsrc) {
    asm volatile("cp.async.ca.shared.global [%0], [%1], 16;" :: "r"(smem_dst), "l"(gsrc));
}
__device__ __forceinline__ void cp_commit() { asm volatile("cp.async.commit_group;"); }
__device__ __forceinline__ void cp_wait1()  { asm volatile("cp.async.wait_group 1;"); }
__device__ __forceinline__ void cp_wait0()  { asm volatile("cp.async.wait_group 0;"); }

#define LDSM4(r, addr) \
    asm volatile("ldmatrix.sync.aligned.m8n8.x4.shared.b16 {%0,%1,%2,%3}, [%4];" \
        : "=r"((r)[0]), "=r"((r)[1]), "=r"((r)[2]), "=r"((r)[3]) : "r"(addr))

__device__ __forceinline__ void mma8(float* c, const uint32_t* a, uint32_t b0, uint32_t b1) {
    asm volatile(
        "mma.sync.aligned.m16n8k8.row.col.f32.tf32.tf32.f32 "
        "{%0,%1,%2,%3}, {%4,%5,%6,%7}, {%8,%9}, {%0,%1,%2,%3};"
        : "+f"(c[0]), "+f"(c[1]), "+f"(c[2]), "+f"(c[3])
        : "r"(a[0]), "r"(a[1]), "r"(a[2]), "r"(a[3]), "r"(b0), "r"(b1));
}

// ---------------- router ----------------
__global__ void router_kernel(const float* __restrict__ x,
                              const float* __restrict__ gw,
                              const float* __restrict__ wsg) {
    int t = blockIdx.x;
    __shared__ float xs[H_DIM];
    __shared__ float logits[E_NUM + 1];
    const float4* xr = (const float4*)(x + (size_t)t * H_DIM);
    for (int i = threadIdx.x; i < H_DIM / 4; i += blockDim.x)
        ((float4*)xs)[i] = xr[i];
    __syncthreads();
    int warp = threadIdx.x >> 5, lane = threadIdx.x & 31;
    for (int u = warp; u < E_NUM + 1; u += 8) {
        const float4* wrow = (const float4*)((u < E_NUM) ? (gw + (size_t)u * H_DIM) : wsg);
        float s = 0.f;
        for (int i = lane; i < H_DIM / 4; i += 32) {
            float4 a = ((const float4*)xs)[i];
            float4 b = wrow[i];
            s += a.x * b.x + a.y * b.y + a.z * b.z + a.w * b.w;
        }
        #pragma unroll
        for (int o = 16; o; o >>= 1) s += __shfl_xor_sync(0xffffffffu, s, o);
        if (lane == 0) logits[u] = s;
    }
    __syncthreads();
    if (threadIdx.x == 0) {
        unsigned long long used = 0ull;
        float vals[TOPK]; int idx[TOPK];
        for (int k = 0; k < TOPK; k++) {
            float best = -INFINITY; int bi = 0;
            for (int e = 0; e < E_NUM; e++)
                if (!((used >> e) & 1ull) && logits[e] > best) { best = logits[e]; bi = e; }
            used |= 1ull << bi; vals[k] = best; idx[k] = bi;
        }
        float m = vals[0], sum = 0.f, w[TOPK];
        for (int k = 0; k < TOPK; k++) { w[k] = expf(vals[k] - m); sum += w[k]; }
        float inv = 1.f / sum;
        for (int k = 0; k < TOPK; k++) {
            d_topk_w[t * TOPK + k]  = w[k] * inv;
            d_topk_idx[t * TOPK + k] = idx[k];
        }
        d_sgate[t] = logits[E_NUM];
    }
}

// ------- dispatch: stable rank within expert -------
__global__ void dispatch_kernel() {
    int e = blockIdx.x;
    __shared__ int warp_sums[8];
    __shared__ int base_s;
    if (threadIdx.x == 0) base_s = 0;
    int lane = threadIdx.x & 31, warp = threadIdx.x >> 5;
    for (int c = 0; c < T_TOK * TOPK; c += 256) {
        __syncthreads();
        int i = c + threadIdx.x;
        bool m = (d_topk_idx[i] == e);
        unsigned mask = __ballot_sync(0xffffffffu, m);
        if (lane == 0) warp_sums[warp] = __popc(mask);
        __syncthreads();
        int off = 0, total = 0;
        #pragma unroll
        for (int w = 0; w < 8; w++) { int v = warp_sums[w]; total += v; if (w < warp) off += v; }
        if (m) {
            int pos = base_s + off + __popc(mask & ((1u << lane) - 1u));
            d_pos[i] = pos;
            if (pos < CAP) d_toklist[e * CAP + pos] = i >> 3;
        }
        __syncthreads();
        if (threadIdx.x == 0) base_s += total;
    }
    __syncthreads();
    if (threadIdx.x == 0) d_cnt[e] = min(base_s, CAP);
}

// ========== dual GEMM + SwiGLU: Out = silu(A@B1) * (A@B3) ==========
// 256 threads, 8 warps (4m x 2n). Block 128x64 (x2 mats). Warp tile 32x32/mat.
// A smem [m][k] raw fp32 (cp.async), consumer cvt. B smem [n][k] tf32 (producer cvt).
__global__ void __launch_bounds__(256, 2)
mm_dual(const float* __restrict__ A, int lda, size_t strideA,
        const int* __restrict__ gather, const int* __restrict__ cnt,
        int mfull, int mtiles,
        const float* __restrict__ B1g, const float* __restrict__ B3g,
        int ldb, size_t strideB,
        float* __restrict__ Out, int ldo, size_t strideOut, int K) {
    extern __shared__ __align__(16) unsigned char smraw[];
    uint32_t smb = smem_u32(smraw);

    int e = blockIdx.x / mtiles, mt = blockIdx.x - e * mtiles;
    int noff = blockIdx.y * 64;
    int nrows = cnt ? cnt[e] - mt * 128 : mfull - mt * 128;
    if (nrows <= 0) return;
    int valid = min(128, nrows);

    int tid = threadIdx.x, wid = tid >> 5, lane = tid & 31;
    int wm = wid & 3, wn = wid >> 2;
    int g = lane >> 2, t4 = lane & 3;

    // A producer: 4 float4/thread via cp.async (raw fp32)
    const float* ap[4]; uint32_t asts[4];
    {
        int c4 = tid & 7, arow0 = tid >> 3;
        #pragma unroll
        for (int jj = 0; jj < 4; jj++) {
            int r = arow0 + jj * 32;
            int rr = min(r, valid - 1);
            long gr = gather ? (long)gather[e * CAP + mt * 128 + rr] : (long)(mt * 128 + rr);
            ap[jj] = A + (size_t)e * strideA + (size_t)gr * lda + c4 * 4;
            asts[jj] = (uint32_t)(r * ROWB + c4 * 16);
        }
    }
    // B producer: 2 float4/thread/mat, transposed STS into [n][k]
    const float *b1p[2], *b3p[2]; uint32_t bsts[2];
    #pragma unroll
    for (int jj = 0; jj < 2; jj++) {
        int idx = tid + 256 * jj;
        int kq = idx & 31, n4 = (idx >> 5) * 4;
        size_t go = (size_t)e * strideB + (size_t)kq * ldb + noff + n4;
        b1p[jj] = B1g + go;
        b3p[jj] = B3g + go;
        bsts[jj] = (uint32_t)(n4 * ROWB + kq * 4);
    }

    // ldmatrix lane offsets (A: a0/a1/a2/a3 tile order; B: j0b0/j0b1/j1b0/j1b1)
    uint32_t aoff[2];
    #pragma unroll
    for (int mf = 0; mf < 2; mf++) {
        int row = wm * 32 + mf * 16 + (lane & 7) + ((lane >> 3) & 1) * 8;
        aoff[mf] = (uint32_t)(row * ROWB + ((lane >> 4) & 1) * 16);
    }
    uint32_t boff[2];
    #pragma unroll
    for (int gp = 0; gp < 2; gp++) {
        int row = wn * 32 + gp * 16 + (lane & 7) + ((lane >> 4) & 1) * 8;
        boff[gp] = (uint32_t)(row * ROWB + ((lane >> 3) & 1) * 16);
    }

    float c1[2][4][4], c3[2][4][4];
    #pragma unroll
    for (int a = 0; a < 2; a++)
        #pragma unroll
        for (int b = 0; b < 4; b++)
            #pragma unroll
            for (int r = 0; r < 4; r++) { c1[a][b][r] = 0.f; c3[a][b][r] = 0.f; }

    float4 rb1[2], rb3[2];
    auto ldgB = [&]() {
        #pragma unroll
        for (int jj = 0; jj < 2; jj++) {
            rb1[jj] = *(const float4*)b1p[jj]; b1p[jj] += (size_t)BK * ldb;
            rb3[jj] = *(const float4*)b3p[jj]; b3p[jj] += (size_t)BK * ldb;
        }
    };
    auto cpA = [&](int s) {
        uint32_t ab = smb + s * STG;
        #pragma unroll
        for (int jj = 0; jj < 4; jj++) {
            cp16(ab + asts[jj], ap[jj]);
            ap[jj] += BK;
        }
    };
    auto stsB = [&](int s) {
        uint32_t bb = smb + s * STG + A_BYTES;
        #pragma unroll
        for (int jj = 0; jj < 2; jj++) {
            uint32_t b1a = bb + bsts[jj];
            asm volatile("st.shared.b32 [%0], %1;" :: "r"(b1a),            "r"(tf32r(rb1[jj].x)));
            asm volatile("st.shared.b32 [%0], %1;" :: "r"(b1a + ROWB),     "r"(tf32r(rb1[jj].y)));
            asm volatile("st.shared.b32 [%0], %1;" :: "r"(b1a + 2 * ROWB), "r"(tf32r(rb1[jj].z)));
            asm volatile("st.shared.b32 [%0], %1;" :: "r"(b1a + 3 * ROWB), "r"(tf32r(rb1[jj].w)));
            uint32_t b3a = b1a + 64 * ROWB;
            asm volatile("st.shared.b32 [%0], %1;" :: "r"(b3a),            "r"(tf32r(rb3[jj].x)));
            asm volatile("st.shared.b32 [%0], %1;" :: "r"(b3a + ROWB),     "r"(tf32r(rb3[jj].y)));
            asm volatile("st.shared.b32 [%0], %1;" :: "r"(b3a + 2 * ROWB), "r"(tf32r(rb3[jj].z)));
            asm volatile("st.shared.b32 [%0], %1;" :: "r"(b3a + 3 * ROWB), "r"(tf32r(rb3[jj].w)));
        }
    };

    int nk = K / BK;
    ldgB();
    cpA(0); cp_commit();
    for (int i = 0; i < nk; i++) {
        int s = i & 1;
        stsB(s);
        bool more = (i + 1 < nk);
        if (more) { ldgB(); cpA(s ^ 1); cp_commit(); cp_wait1(); }
        else cp_wait0();
        __syncthreads();
        uint32_t ab = smb + s * STG;
        uint32_t bb = ab + A_BYTES;
        #pragma unroll
        for (int kk = 0; kk < 4; kk++) {
            uint32_t af[2][4], bf1[2][4], bf3[2][4];
            LDSM4(af[0], ab + aoff[0] + kk * 32);
            LDSM4(af[1], ab + aoff[1] + kk * 32);
            #pragma unroll
            for (int mf = 0; mf < 2; mf++)
                #pragma unroll
                for (int q = 0; q < 4; q++) af[mf][q] = tf32b(af[mf][q]);
            LDSM4(bf1[0], bb + boff[0] + kk * 32);
            LDSM4(bf1[1], bb + boff[1] + kk * 32);
            LDSM4(bf3[0], bb + 64 * ROWB + boff[0] + kk * 32);
            LDSM4(bf3[1], bb + 64 * ROWB + boff[1] + kk * 32);
            #pragma unroll
            for (int mf = 0; mf < 2; mf++)
                #pragma unroll
                for (int gp = 0; gp < 2; gp++)
                    #pragma unroll
                    for (int j = 0; j < 2; j++) {
                        mma8(c1[mf][gp * 2 + j], af[mf], bf1[gp][j * 2], bf1[gp][j * 2 + 1]);
                        mma8(c3[mf][gp * 2 + j], af[mf], bf3[gp][j * 2], bf3[gp][j * 2 + 1]);
                    }
        }
        __syncthreads();
    }

    float* outp = Out + (size_t)e * strideOut + (size_t)(mt * 128) * ldo + noff;
    #pragma unroll
    for (int mf = 0; mf < 2; mf++)
        #pragma unroll
        for (int nf = 0; nf < 4; nf++) {
            int r0 = wm * 32 + mf * 16 + g;
            int cc = wn * 32 + nf * 8 + t4 * 2;
            #pragma unroll
            for (int h = 0; h < 2; h++) {
                int r = r0 + h * 8;
                if (r < valid) {
                    float v1a = c1[mf][nf][h * 2 + 0], v3a = c3[mf][nf][h * 2 + 0];
                    float v1b = c1[mf][nf][h * 2 + 1], v3b = c3[mf][nf][h * 2 + 1];
                    float ga = (v1a / (1.f + expf(-v1a))) * v3a;
                    float gb = (v1b / (1.f + expf(-v1b))) * v3b;
                    *(float2*)(outp + (size_t)r * ldo + cc) = make_float2(ga, gb);
                }
            }
        }
}

// ========== single GEMM: Out = A @ B ==========
// 256 threads, 8 warps (4m x 2n). Block 128x128. Warp tile 32x64.
__global__ void __launch_bounds__(256, 2)
mm_single(const float* __restrict__ A, int lda, size_t strideA,
          const int* __restrict__ cnt, int mfull, int mtiles,
          const float* __restrict__ Bg, int ldb, size_t strideB,
          float* __restrict__ Out, int ldo, size_t strideOut, int K) {
    extern __shared__ __align__(16) unsigned char smraw[];
    uint32_t smb = smem_u32(smraw);

    int e = blockIdx.x / mtiles, mt = blockIdx.x - e * mtiles;
    int noff = blockIdx.y * 128;
    int nrows = cnt ? cnt[e] - mt * 128 : mfull - mt * 128;
    if (nrows <= 0) return;
    int valid = min(128, nrows);

    int tid = threadIdx.x, wid = tid >> 5, lane = tid & 31;
    int wm = wid & 3, wn = wid >> 2;
    int g = lane >> 2, t4 = lane & 3;

    const float* ap[4]; uint32_t asts[4];
    {
        int c4 = tid & 7, arow0 = tid >> 3;
        #pragma unroll
        for (int jj = 0; jj < 4; jj++) {
            int r = arow0 + jj * 32;
            ap[jj] = A + (size_t)e * strideA + (size_t)(mt * 128 + r) * lda + c4 * 4;
            asts[jj] = (uint32_t)(r * ROWB + c4 * 16);
        }
    }
    const float* bp[4]; uint32_t bsts[4];
    #pragma unroll
    for (int jj = 0; jj < 4; jj++) {
        int idx = tid + 256 * jj;
        int kq = idx & 31, n4 = (idx >> 5) * 4;
        bp[jj] = Bg + (size_t)e * strideB + (size_t)kq * ldb + noff + n4;
        bsts[jj] = (uint32_t)(n4 * ROWB + kq * 4);
    }

    uint32_t aoff[2];
    #pragma unroll
    for (int mf = 0; mf < 2; mf++) {
        int row = wm * 32 + mf * 16 + (lane & 7) + ((lane >> 3) & 1) * 8;
        aoff[mf] = (uint32_t)(row * ROWB + ((lane >> 4) & 1) * 16);
    }
    uint32_t boff[4];
    #pragma unroll
    for (int gp = 0; gp < 4; gp++) {
        int row = wn * 64 + gp * 16 + (lane & 7) + ((lane >> 4) & 1) * 8;
        boff[gp] = (uint32_t)(row * ROWB + ((lane >> 3) & 1) * 16);
    }

    float c[2][8][4];
    #pragma unroll
    for (int a = 0; a < 2; a++)
        #pragma unroll
        for (int b = 0; b < 8; b++)
            #pragma unroll
            for (int r = 0; r < 4; r++) c[a][b][r] = 0.f;

    float4 rb[4];
    auto ldgB = [&]() {
        #pragma unroll
        for (int jj = 0; jj < 4; jj++) { rb[jj] = *(const float4*)bp[jj]; bp[jj] += (size_t)BK * ldb; }
    };
    auto cpA = [&](int s) {
        uint32_t ab = smb + s * STG;
        #pragma unroll
        for (int jj = 0; jj < 4; jj++) { cp16(ab + asts[jj], ap[jj]); ap[jj] += BK; }
    };
    auto stsB = [&](int s) {
        uint32_t bb = smb + s * STG + A_BYTES;
        #pragma unroll
        for (int jj = 0; jj < 4; jj++) {
            uint32_t ba = bb + bsts[jj];
            asm volatile("st.shared.b32 [%0], %1;" :: "r"(ba),            "r"(tf32r(rb[jj].x)));
            asm volatile("st.shared.b32 [%0], %1;" :: "r"(ba + ROWB),     "r"(tf32r(rb[jj].y)));
            asm volatile("st.shared.b32 [%0], %1;" :: "r"(ba + 2 * ROWB), "r"(tf32r(rb[jj].z)));
            asm volatile("st.shared.b32 [%0], %1;" :: "r"(ba + 3 * ROWB), "r"(tf32r(rb[jj].w)));
        }
    };

    int nk = K / BK;
    ldgB();
    cpA(0); cp_commit();
    for (int i = 0; i < nk; i++) {
        int s = i & 1;
        stsB(s);
        bool more = (i + 1 < nk);
        if (more) { ldgB(); cpA(s ^ 1); cp_commit(); cp_wait1(); }
        else cp_wait0();
        __syncthreads();
        uint32_t ab = smb + s * STG;
        uint32_t bb = ab + A_BYTES;
        #pragma unroll
        for (int kk = 0; kk < 4; kk++) {
            uint32_t af[2][4], bf[4][4];
            LDSM4(af[0], ab + aoff[0] + kk * 32);
            LDSM4(af[1], ab + aoff[1] + kk * 32);
            #pragma unroll
            for (int mf = 0; mf < 2; mf++)
                #pragma unroll
                for (int q = 0; q < 4; q++) af[mf][q] = tf32b(af[mf][q]);
            #pragma unroll
            for (int gp = 0; gp < 4; gp++) LDSM4(bf[gp], bb + boff[gp] + kk * 32);
            #pragma unroll
            for (int mf = 0; mf < 2; mf++)
                #pragma unroll
                for (int gp = 0; gp < 4; gp++)
                    #pragma unroll
                    for (int j = 0; j < 2; j++)
                        mma8(c[mf][gp * 2 + j], af[mf], bf[gp][j * 2], bf[gp][j * 2 + 1]);
        }
        __syncthreads();
    }

    float* outp = Out + (size_t)e * strideOut + (size_t)(mt * 128) * ldo + noff;
    #pragma unroll
    for (int mf = 0; mf < 2; mf++)
        #pragma unroll
        for (int nf = 0; nf < 8; nf++) {
            int r0 = wm * 32 + mf * 16 + g;
            int cc = wn * 64 + nf * 8 + t4 * 2;
            #pragma unroll
            for (int h = 0; h < 2; h++) {
                int r = r0 + h * 8;
                if (r < valid)
                    *(float2*)(outp + (size_t)r * ldo + cc) =
                        make_float2(c[mf][nf][h * 2 + 0], c[mf][nf][h * 2 + 1]);
            }
        }
}

// ---------------- combine: routed + sigmoid-gated shared ----------------
__global__ void combine_kernel(float* __restrict__ out) {
    int t = blockIdx.x;
    __shared__ int rows[TOPK];
    __shared__ float ws[TOPK];
    if (threadIdx.x < TOPK) {
        int k = threadIdx.x;
        int ee = d_topk_idx[t * TOPK + k];
        int p  = d_pos[t * TOPK + k];
        rows[k] = (p < CAP) ? (ee * CAP + p) : -1;
        ws[k] = d_topk_w[t * TOPK + k];
    }
    __syncthreads();
    float sg = 1.f / (1.f + expf(-d_sgate[t]));
    #pragma unroll
    for (int j = 0; j < 2; j++) {
        int h = threadIdx.x * 4 + j * 1024;
        float4 acc = *(const float4*)(d_s2 + (size_t)t * H_DIM + h);
        acc.x *= sg; acc.y *= sg; acc.z *= sg; acc.w *= sg;
        #pragma unroll
        for (int k = 0; k < TOPK; k++) {
            int r = rows[k];
            if (r >= 0) {
                float w = ws[k];
                float4 y = *(const float4*)(d_yb + (size_t)r * H_DIM + h);
                acc.x += w * y.x; acc.y += w * y.y; acc.z += w * y.z; acc.w += w * y.w;
            }
        }
        *(float4*)(out + (size_t)t * H_DIM + h) = acc;
    }
}

// ---------------- launch ----------------
extern "C" void kernel_launch(void* const* d_in, const int* in_sizes, int n_in,
                              void* d_out, int out_size) {
    (void)in_sizes; (void)n_in; (void)out_size;
    const float* x   = (const float*)d_in[0];
    const float* gw  = (const float*)d_in[1];
    const float* w1  = (const float*)d_in[2];
    const float* w3  = (const float*)d_in[3];
    const float* w2  = (const float*)d_in[4];
    const float* ws1 = (const float*)d_in[5];
    const float* ws3 = (const float*)d_in[6];
    const float* ws2 = (const float*)d_in[7];
    const float* wsg = (const float*)d_in[8];
    float* out = (float*)d_out;

    cudaFuncSetAttribute(mm_dual,   cudaFuncAttributeMaxDynamicSharedMemorySize, SM_MM);
    cudaFuncSetAttribute(mm_single, cudaFuncAttributeMaxDynamicSharedMemorySize, SM_MM);

    float *gbuf, *yb, *s1, *s2;
    int *cnt, *toklist;
    cudaGetSymbolAddress((void**)&gbuf, d_gbuf);
    cudaGetSymbolAddress((void**)&yb, d_yb);
    cudaGetSymbolAddress((void**)&s1, d_s1);
    cudaGetSymbolAddress((void**)&s2, d_s2);
    cudaGetSymbolAddress((void**)&cnt, d_cnt);
    cudaGetSymbolAddress((void**)&toklist, d_toklist);

    router_kernel<<<T_TOK, 256>>>(x, gw, wsg);
    dispatch_kernel<<<E_NUM, 256>>>();

    // experts: G = silu(X@w1) * (X@w3)   [gathered rows]
    mm_dual<<<dim3(E_NUM * 2, I_DIM / 64), 256, SM_MM>>>(
        x, H_DIM, 0, toklist, cnt, 0, 2,
        w1, w3, I_DIM, (size_t)H_DIM * I_DIM,
        gbuf, I_DIM, (size_t)CAP * I_DIM, H_DIM);

    // shared: S1 = silu(X@ws1) * (X@ws3)
    mm_dual<<<dim3(8, IS_DIM / 64), 256, SM_MM>>>(
        x, H_DIM, 0, nullptr, nullptr, T_TOK, 8,
        ws1, ws3, IS_DIM, 0,
        s1, IS_DIM, 0, H_DIM);

    // experts: Y = G @ w2
    mm_single<<<dim3(E_NUM * 2, H_DIM / 128), 256, SM_MM>>>(
        gbuf, I_DIM, (size_t)CAP * I_DIM, cnt, 0, 2,
        w2, H_DIM, (size_t)I_DIM * H_DIM,
        yb, H_DIM, (size_t)CAP * H_DIM, I_DIM);

    // shared: S2 = S1 @ ws2
    mm_single<<<dim3(8, H_DIM / 128), 256, SM_MM>>>(
        s1, IS_DIM, 0, nullptr, T_TOK, 8,
        ws2, H_DIM, 0,
        s2, H_DIM, 0, IS_DIM);

    combine_kernel<<<T_TOK, 256>>>(out);
}

// round 8
// speedup vs baseline: 1.4777x; 1.2241x over previous
#include <cuda_runtime.h>
#include <cstdint>
#include <math.h>

#define T_TOK 1024
#define H_DIM 2048
#define E_NUM 64
#define I_DIM 512
#define IS_DIM 1024
#define TOPK 8
#define CAP 256

// ---------------- scratch (static device globals; no allocs) ----------------
__device__ int   d_topk_idx[T_TOK * TOPK];
__device__ float d_topk_w[T_TOK * TOPK];
__device__ float d_sgate[T_TOK];
__device__ int   d_cnt[E_NUM];
__device__ int   d_toklist[E_NUM * CAP];
__device__ int   d_pos[T_TOK * TOPK];
__device__ float d_gbuf[(size_t)E_NUM * CAP * I_DIM];
__device__ float d_yb[(size_t)E_NUM * CAP * H_DIM];
__device__ float d_s1[(size_t)T_TOK * IS_DIM];
__device__ float d_s2[(size_t)T_TOK * H_DIM];

// ---------------- helpers ----------------
__device__ __forceinline__ unsigned tf32r(float x) {
    unsigned r;
    asm("cvt.rna.tf32.f32 %0, %1;" : "=r"(r) : "f"(x));
    return r;
}

__device__ __forceinline__ void mma8(float* c, unsigned a0, unsigned a1, unsigned a2,
                                     unsigned a3, unsigned b0, unsigned b1) {
    asm volatile(
        "mma.sync.aligned.m16n8k8.row.col.f32.tf32.tf32.f32 "
        "{%0,%1,%2,%3}, {%4,%5,%6,%7}, {%8,%9}, {%0,%1,%2,%3};"
        : "+f"(c[0]), "+f"(c[1]), "+f"(c[2]), "+f"(c[3])
        : "r"(a0), "r"(a1), "r"(a2), "r"(a3), "r"(b0), "r"(b1));
}

__device__ __forceinline__ void cp16(void* smem_dst, const void* gsrc) {
    unsigned d = (unsigned)__cvta_generic_to_shared(smem_dst);
    asm volatile("cp.async.ca.shared.global [%0], [%1], 16;" :: "r"(d), "l"(gsrc));
}
__device__ __forceinline__ void cp_commit() { asm volatile("cp.async.commit_group;"); }
__device__ __forceinline__ void cp_wait1()  { asm volatile("cp.async.wait_group 1;"); }
__device__ __forceinline__ void cp_wait0()  { asm volatile("cp.async.wait_group 0;"); }
__device__ __forceinline__ void sts128(float* dst, unsigned a, unsigned b, unsigned c, unsigned d) {
    unsigned p = (unsigned)__cvta_generic_to_shared(dst);
    asm volatile("st.shared.v4.b32 [%0], {%1,%2,%3,%4};" :: "r"(p), "r"(a), "r"(b), "r"(c), "r"(d));
}

// ---------------- router: logits, top-8, softmax, shared gate ----------------
__global__ void router_kernel(const float* __restrict__ x,
                              const float* __restrict__ gw,
                              const float* __restrict__ wsg) {
    int t = blockIdx.x;
    __shared__ float xs[H_DIM];
    __shared__ float logits[E_NUM + 1];
    const float4* xr = (const float4*)(x + (size_t)t * H_DIM);
    for (int i = threadIdx.x; i < H_DIM / 4; i += blockDim.x)
        ((float4*)xs)[i] = xr[i];
    __syncthreads();
    int warp = threadIdx.x >> 5, lane = threadIdx.x & 31;
    for (int u = warp; u < E_NUM + 1; u += 8) {
        const float4* wrow = (const float4*)((u < E_NUM) ? (gw + (size_t)u * H_DIM) : wsg);
        float s = 0.f;
        for (int i = lane; i < H_DIM / 4; i += 32) {
            float4 a = ((const float4*)xs)[i];
            float4 b = wrow[i];
            s += a.x * b.x + a.y * b.y + a.z * b.z + a.w * b.w;
        }
        #pragma unroll
        for (int o = 16; o; o >>= 1) s += __shfl_xor_sync(0xffffffffu, s, o);
        if (lane == 0) logits[u] = s;
    }
    __syncthreads();
    if (threadIdx.x == 0) {
        unsigned long long used = 0ull;
        float vals[TOPK]; int idx[TOPK];
        for (int k = 0; k < TOPK; k++) {
            float best = -INFINITY; int bi = 0;
            for (int e = 0; e < E_NUM; e++)
                if (!((used >> e) & 1ull) && logits[e] > best) { best = logits[e]; bi = e; }
            used |= 1ull << bi; vals[k] = best; idx[k] = bi;
        }
        float m = vals[0], sum = 0.f, w[TOPK];
        for (int k = 0; k < TOPK; k++) { w[k] = expf(vals[k] - m); sum += w[k]; }
        float inv = 1.f / sum;
        for (int k = 0; k < TOPK; k++) {
            d_topk_w[t * TOPK + k]  = w[k] * inv;
            d_topk_idx[t * TOPK + k] = idx[k];
        }
        d_sgate[t] = logits[E_NUM];
    }
}

// ------- dispatch: stable rank within expert over flat (token,slot) order -------
__global__ void dispatch_kernel() {
    int e = blockIdx.x;
    __shared__ int warp_sums[8];
    __shared__ int base_s;
    if (threadIdx.x == 0) base_s = 0;
    int lane = threadIdx.x & 31, warp = threadIdx.x >> 5;
    for (int c = 0; c < T_TOK * TOPK; c += 256) {
        __syncthreads();
        int i = c + threadIdx.x;
        bool m = (d_topk_idx[i] == e);
        unsigned mask = __ballot_sync(0xffffffffu, m);
        if (lane == 0) warp_sums[warp] = __popc(mask);
        __syncthreads();
        int off = 0, total = 0;
        #pragma unroll
        for (int w = 0; w < 8; w++) { int v = warp_sums[w]; total += v; if (w < warp) off += v; }
        if (m) {
            int pos = base_s + off + __popc(mask & ((1u << lane) - 1u));
            d_pos[i] = pos;
            if (pos < CAP) d_toklist[e * CAP + pos] = i >> 3;
        }
        __syncthreads();
        if (threadIdx.x == 0) base_s += total;
    }
    __syncthreads();
    if (threadIdx.x == 0) d_cnt[e] = min(base_s, CAP);
}

// ---------------- dual GEMM (C1=A@B1, C3=A@B3) + SwiGLU epilogue ----------------
// 256 threads, 8 warps (4m x 2n), block tile 128x64 (per matrix), warp tile 32x32.
// A: cp.async raw fp32, consumer cvt. B: LDG->cvt.rna->STS128 (tf32 bits in smem).
#define BM 128
#define BKx 32
#define ASTR 36
#define BSTR_D 72
#define SMEM_DUAL ((2 * BM * ASTR + 2 * 2 * BKx * BSTR_D) * 4)

__global__ void __launch_bounds__(256, 2)
dual_gemm_silu(const float* __restrict__ A, int lda, size_t strideA,
               const int* __restrict__ gather, const int* __restrict__ cnt,
               int mfull, int mtiles,
               const float* __restrict__ B1g, const float* __restrict__ B3g,
               int ldb, size_t strideB,
               float* __restrict__ Out, int ldo, size_t strideOut, int K) {
    extern __shared__ float sm[];
    float* As  = sm;                       // 2 * 128 * 36
    float* B1s = sm + 2 * BM * ASTR;       // 2 * 32 * 72
    float* B3s = B1s + 2 * BKx * BSTR_D;   // 2 * 32 * 72

    int e = blockIdx.x / mtiles;
    int mt = blockIdx.x - e * mtiles;
    int noff = blockIdx.y * 64;
    int nrows = cnt ? (cnt[e] - mt * BM) : (mfull - mt * BM);
    if (nrows <= 0) return;
    int valid = min(BM, nrows);

    int tid = threadIdx.x;
    int acol = (tid & 7) * 4;
    int arow0 = tid >> 3;                  // 0..31
    const float* aptr[4];
    #pragma unroll
    for (int i = 0; i < 4; i++) {
        int r = arow0 + i * 32;
        int rr = min(r, valid - 1);
        long grow = gather ? (long)gather[e * CAP + mt * BM + rr] : ((long)mt * BM + rr);
        aptr[i] = A + (size_t)e * strideA + (size_t)grow * lda + acol;
    }
    const float* b1ptr[2];
    const float* b3ptr[2];
    int bk_[2], bn4_[2];
    {
        const float* B1 = B1g + (size_t)e * strideB + noff;
        const float* B3 = B3g + (size_t)e * strideB + noff;
        #pragma unroll
        for (int i = 0; i < 2; i++) {
            int slot = tid + i * 256;
            bk_[i] = slot >> 4;             // 0..31
            bn4_[i] = (slot & 15) * 4;      // 0..60
            b1ptr[i] = B1 + (size_t)bk_[i] * ldb + bn4_[i];
            b3ptr[i] = B3 + (size_t)bk_[i] * ldb + bn4_[i];
        }
    }

    float c1[2][4][4], c3[2][4][4];
    #pragma unroll
    for (int a = 0; a < 2; a++)
        #pragma unroll
        for (int b = 0; b < 4; b++)
            #pragma unroll
            for (int r = 0; r < 4; r++) { c1[a][b][r] = 0.f; c3[a][b][r] = 0.f; }

    int warp = tid >> 5, lane = tid & 31;
    int wm = warp & 3, wn = warp >> 2;     // 4m x 2n
    int g = lane >> 2, t4 = lane & 3;

    float4 rb1[2], rb3[2];
    auto ldgB = [&]() {
        #pragma unroll
        for (int i = 0; i < 2; i++) {
            rb1[i] = *(const float4*)b1ptr[i]; b1ptr[i] += (size_t)BKx * ldb;
            rb3[i] = *(const float4*)b3ptr[i]; b3ptr[i] += (size_t)BKx * ldb;
        }
    };
    auto cpA = [&](int s) {
        float* as = As + s * BM * ASTR;
        #pragma unroll
        for (int i = 0; i < 4; i++) {
            int r = arow0 + i * 32;
            cp16(as + r * ASTR + acol, aptr[i]);
            aptr[i] += BKx;
        }
    };
    auto stsB = [&](int s) {
        float* b1s = B1s + s * BKx * BSTR_D;
        float* b3s = B3s + s * BKx * BSTR_D;
        #pragma unroll
        for (int i = 0; i < 2; i++) {
            int doff = bk_[i] * BSTR_D + bn4_[i];
            sts128(b1s + doff, tf32r(rb1[i].x), tf32r(rb1[i].y), tf32r(rb1[i].z), tf32r(rb1[i].w));
            sts128(b3s + doff, tf32r(rb3[i].x), tf32r(rb3[i].y), tf32r(rb3[i].z), tf32r(rb3[i].w));
        }
    };

    int nk = K / BKx;
    ldgB();
    cpA(0); cp_commit();
    for (int kb = 0; kb < nk; kb++) {
        int s = kb & 1;
        stsB(s);
        if (kb + 1 < nk) {
            ldgB();
            cpA(s ^ 1); cp_commit(); cp_wait1();
        } else {
            cp_wait0();
        }
        __syncthreads();
        const float* as  = As + s * BM * ASTR;
        const float* b1s = B1s + s * BKx * BSTR_D;
        const float* b3s = B3s + s * BKx * BSTR_D;
        #pragma unroll
        for (int kk = 0; kk < 4; kk++) {
            int kc = kk * 8 + t4;
            unsigned af[2][4];
            #pragma unroll
            for (int mf = 0; mf < 2; mf++) {
                int r0 = wm * 32 + mf * 16 + g;
                af[mf][0] = tf32r(as[r0 * ASTR + kc]);
                af[mf][1] = tf32r(as[(r0 + 8) * ASTR + kc]);
                af[mf][2] = tf32r(as[r0 * ASTR + kc + 4]);
                af[mf][3] = tf32r(as[(r0 + 8) * ASTR + kc + 4]);
            }
            unsigned bf1[4][2], bf3[4][2];
            #pragma unroll
            for (int nf = 0; nf < 4; nf++) {
                int nn = wn * 32 + nf * 8 + g;
                bf1[nf][0] = __float_as_uint(b1s[kc * BSTR_D + nn]);
                bf1[nf][1] = __float_as_uint(b1s[(kc + 4) * BSTR_D + nn]);
                bf3[nf][0] = __float_as_uint(b3s[kc * BSTR_D + nn]);
                bf3[nf][1] = __float_as_uint(b3s[(kc + 4) * BSTR_D + nn]);
            }
            #pragma unroll
            for (int mf = 0; mf < 2; mf++)
                #pragma unroll
                for (int nf = 0; nf < 4; nf++) {
                    mma8(c1[mf][nf], af[mf][0], af[mf][1], af[mf][2], af[mf][3], bf1[nf][0], bf1[nf][1]);
                    mma8(c3[mf][nf], af[mf][0], af[mf][1], af[mf][2], af[mf][3], bf3[nf][0], bf3[nf][1]);
                }
        }
        __syncthreads();
    }

    float* outp = Out + (size_t)e * strideOut + (size_t)mt * BM * ldo + noff;
    #pragma unroll
    for (int mf = 0; mf < 2; mf++)
        #pragma unroll
        for (int nf = 0; nf < 4; nf++) {
            int r0 = wm * 32 + mf * 16 + g;
            int cc = wn * 32 + nf * 8 + t4 * 2;
            #pragma unroll
            for (int h = 0; h < 2; h++) {
                int r = r0 + h * 8;
                if (r < valid) {
                    float v1a = c1[mf][nf][h * 2 + 0], v3a = c3[mf][nf][h * 2 + 0];
                    float v1b = c1[mf][nf][h * 2 + 1], v3b = c3[mf][nf][h * 2 + 1];
                    float ga = (v1a / (1.f + expf(-v1a))) * v3a;
                    float gb = (v1b / (1.f + expf(-v1b))) * v3b;
                    *(float2*)(outp + (size_t)r * ldo + cc) = make_float2(ga, gb);
                }
            }
        }
}

// ---------------- single GEMM (C = A @ B) ----------------
// 256 threads, 8 warps (4m x 2n), block tile 128x128, warp tile 32x64.
#define BSTR_S 136
#define SMEM_SINGLE ((2 * BM * ASTR + 2 * BKx * BSTR_S) * 4)

__global__ void __launch_bounds__(256, 2)
single_gemm(const float* __restrict__ A, int lda, size_t strideA,
            const int* __restrict__ cnt, int mfull, int mtiles,
            const float* __restrict__ Bg, int ldb, size_t strideB,
            float* __restrict__ Out, int ldo, size_t strideOut, int K) {
    extern __shared__ float sm[];
    float* As = sm;                      // 2 * 128 * 36
    float* Bs = sm + 2 * BM * ASTR;      // 2 * 32 * 136

    int e = blockIdx.x / mtiles;
    int mt = blockIdx.x - e * mtiles;
    int noff = blockIdx.y * 128;
    int nrows = cnt ? (cnt[e] - mt * BM) : (mfull - mt * BM);
    if (nrows <= 0) return;
    int valid = min(BM, nrows);

    int tid = threadIdx.x;
    int acol = (tid & 7) * 4;
    int arow0 = tid >> 3;                // 0..31
    const float* aptr[4];
    #pragma unroll
    for (int i = 0; i < 4; i++) {
        int r = arow0 + i * 32;
        int rr = min(r, valid - 1);
        aptr[i] = A + (size_t)e * strideA + ((size_t)mt * BM + rr) * lda + acol;
    }
    const float* bptr[4];
    int bk_[4], bn4_[4];
    {
        const float* B = Bg + (size_t)e * strideB + noff;
        #pragma unroll
        for (int i = 0; i < 4; i++) {
            int slot = tid + i * 256;
            bk_[i] = slot >> 5;           // 0..31
            bn4_[i] = (slot & 31) * 4;    // 0..124
            bptr[i] = B + (size_t)bk_[i] * ldb + bn4_[i];
        }
    }

    float c[2][8][4];
    #pragma unroll
    for (int a = 0; a < 2; a++)
        #pragma unroll
        for (int b = 0; b < 8; b++)
            #pragma unroll
            for (int r = 0; r < 4; r++) c[a][b][r] = 0.f;

    int warp = tid >> 5, lane = tid & 31;
    int wm = warp & 3, wn = warp >> 2;   // 4m x 2n
    int g = lane >> 2, t4 = lane & 3;

    float4 rb[4];
    auto ldgB = [&]() {
        #pragma unroll
        for (int i = 0; i < 4; i++) { rb[i] = *(const float4*)bptr[i]; bptr[i] += (size_t)BKx * ldb; }
    };
    auto cpA = [&](int s) {
        float* as = As + s * BM * ASTR;
        #pragma unroll
        for (int i = 0; i < 4; i++) {
            int r = arow0 + i * 32;
            cp16(as + r * ASTR + acol, aptr[i]);
            aptr[i] += BKx;
        }
    };
    auto stsB = [&](int s) {
        float* bs = Bs + s * BKx * BSTR_S;
        #pragma unroll
        for (int i = 0; i < 4; i++) {
            int doff = bk_[i] * BSTR_S + bn4_[i];
            sts128(bs + doff, tf32r(rb[i].x), tf32r(rb[i].y), tf32r(rb[i].z), tf32r(rb[i].w));
        }
    };

    int nk = K / BKx;
    ldgB();
    cpA(0); cp_commit();
    for (int kb = 0; kb < nk; kb++) {
        int s = kb & 1;
        stsB(s);
        if (kb + 1 < nk) {
            ldgB();
            cpA(s ^ 1); cp_commit(); cp_wait1();
        } else {
            cp_wait0();
        }
        __syncthreads();
        const float* as = As + s * BM * ASTR;
        const float* bs = Bs + s * BKx * BSTR_S;
        #pragma unroll
        for (int kk = 0; kk < 4; kk++) {
            int kc = kk * 8 + t4;
            unsigned af[2][4];
            #pragma unroll
            for (int mf = 0; mf < 2; mf++) {
                int r0 = wm * 32 + mf * 16 + g;
                af[mf][0] = tf32r(as[r0 * ASTR + kc]);
                af[mf][1] = tf32r(as[(r0 + 8) * ASTR + kc]);
                af[mf][2] = tf32r(as[r0 * ASTR + kc + 4]);
                af[mf][3] = tf32r(as[(r0 + 8) * ASTR + kc + 4]);
            }
            unsigned bf[8][2];
            #pragma unroll
            for (int nf = 0; nf < 8; nf++) {
                int nn = wn * 64 + nf * 8 + g;
                bf[nf][0] = __float_as_uint(bs[kc * BSTR_S + nn]);
                bf[nf][1] = __float_as_uint(bs[(kc + 4) * BSTR_S + nn]);
            }
            #pragma unroll
            for (int mf = 0; mf < 2; mf++)
                #pragma unroll
                for (int nf = 0; nf < 8; nf++)
                    mma8(c[mf][nf], af[mf][0], af[mf][1], af[mf][2], af[mf][3], bf[nf][0], bf[nf][1]);
        }
        __syncthreads();
    }

    float* outp = Out + (size_t)e * strideOut + (size_t)mt * BM * ldo + noff;
    #pragma unroll
    for (int mf = 0; mf < 2; mf++)
        #pragma unroll
        for (int nf = 0; nf < 8; nf++) {
            int r0 = wm * 32 + mf * 16 + g;
            int cc = wn * 64 + nf * 8 + t4 * 2;
            #pragma unroll
            for (int h = 0; h < 2; h++) {
                int r = r0 + h * 8;
                if (r < valid)
                    *(float2*)(outp + (size_t)r * ldo + cc) =
                        make_float2(c[mf][nf][h * 2 + 0], c[mf][nf][h * 2 + 1]);
            }
        }
}

// ---------------- combine: routed + sigmoid-gated shared ----------------
__global__ void combine_kernel(float* __restrict__ out) {
    int t = blockIdx.x;
    __shared__ int rows[TOPK];
    __shared__ float ws[TOPK];
    if (threadIdx.x < TOPK) {
        int k = threadIdx.x;
        int ee = d_topk_idx[t * TOPK + k];
        int p  = d_pos[t * TOPK + k];
        rows[k] = (p < CAP) ? (ee * CAP + p) : -1;
        ws[k] = d_topk_w[t * TOPK + k];
    }
    __syncthreads();
    float sg = 1.f / (1.f + expf(-d_sgate[t]));
    #pragma unroll
    for (int j = 0; j < 2; j++) {
        int h = threadIdx.x * 4 + j * 1024;
        float4 acc = *(const float4*)(d_s2 + (size_t)t * H_DIM + h);
        acc.x *= sg; acc.y *= sg; acc.z *= sg; acc.w *= sg;
        #pragma unroll
        for (int k = 0; k < TOPK; k++) {
            int r = rows[k];
            if (r >= 0) {
                float w = ws[k];
                float4 y = *(const float4*)(d_yb + (size_t)r * H_DIM + h);
                acc.x += w * y.x; acc.y += w * y.y; acc.z += w * y.z; acc.w += w * y.w;
            }
        }
        *(float4*)(out + (size_t)t * H_DIM + h) = acc;
    }
}

// ---------------- launch ----------------
extern "C" void kernel_launch(void* const* d_in, const int* in_sizes, int n_in,
                              void* d_out, int out_size) {
    (void)in_sizes; (void)n_in; (void)out_size;
    const float* x   = (const float*)d_in[0];
    const float* gw  = (const float*)d_in[1];
    const float* w1  = (const float*)d_in[2];
    const float* w3  = (const float*)d_in[3];
    const float* w2  = (const float*)d_in[4];
    const float* ws1 = (const float*)d_in[5];
    const float* ws3 = (const float*)d_in[6];
    const float* ws2 = (const float*)d_in[7];
    const float* wsg = (const float*)d_in[8];
    float* out = (float*)d_out;

    cudaFuncSetAttribute(dual_gemm_silu, cudaFuncAttributeMaxDynamicSharedMemorySize, SMEM_DUAL);
    cudaFuncSetAttribute(single_gemm,    cudaFuncAttributeMaxDynamicSharedMemorySize, SMEM_SINGLE);

    float *gbuf, *yb, *s1, *s2;
    int *cnt, *toklist;
    cudaGetSymbolAddress((void**)&gbuf, d_gbuf);
    cudaGetSymbolAddress((void**)&yb, d_yb);
    cudaGetSymbolAddress((void**)&s1, d_s1);
    cudaGetSymbolAddress((void**)&s2, d_s2);
    cudaGetSymbolAddress((void**)&cnt, d_cnt);
    cudaGetSymbolAddress((void**)&toklist, d_toklist);

    router_kernel<<<T_TOK, 256>>>(x, gw, wsg);
    dispatch_kernel<<<E_NUM, 256>>>();

    // experts: G = silu(X@w1) * (X@w3)   [gathered rows]
    dual_gemm_silu<<<dim3(E_NUM * 2, I_DIM / 64), 256, SMEM_DUAL>>>(
        x, H_DIM, 0, toklist, cnt, 0, 2,
        w1, w3, I_DIM, (size_t)H_DIM * I_DIM,
        gbuf, I_DIM, (size_t)CAP * I_DIM, H_DIM);

    // shared: S1 = silu(X@ws1) * (X@ws3)
    dual_gemm_silu<<<dim3(8, IS_DIM / 64), 256, SMEM_DUAL>>>(
        x, H_DIM, 0, nullptr, nullptr, T_TOK, 8,
        ws1, ws3, IS_DIM, 0,
        s1, IS_DIM, 0, H_DIM);

    // experts: Y = G @ w2
    single_gemm<<<dim3(E_NUM * 2, H_DIM / 128), 256, SMEM_SINGLE>>>(
        gbuf, I_DIM, (size_t)CAP * I_DIM, cnt, 0, 2,
        w2, H_DIM, (size_t)I_DIM * H_DIM,
        yb, H_DIM, (size_t)CAP * H_DIM, I_DIM);

    // shared: S2 = S1 @ ws2
    single_gemm<<<dim3(8, H_DIM / 128), 256, SMEM_SINGLE>>>(
        s1, IS_DIM, 0, nullptr, T_TOK, 8,
        ws2, H_DIM, 0,
        s2, H_DIM, 0, IS_DIM);

    combine_kernel<<<T_TOK, 256>>>(out);
}

// round 9
// speedup vs baseline: 1.7164x; 1.1616x over previous
#include <cuda_runtime.h>
#include <cstdint>
#include <math.h>

#define T_TOK 1024
#define H_DIM 2048
#define E_NUM 64
#define I_DIM 512
#define IS_DIM 1024
#define TOPK 8
#define CAP 256

// ---------------- scratch (static device globals; no allocs) ----------------
__device__ int   d_topk_idx[T_TOK * TOPK];
__device__ float d_topk_w[T_TOK * TOPK];
__device__ float d_sgate[T_TOK];
__device__ int   d_cnt[E_NUM];
__device__ int   d_toklist[E_NUM * CAP];
__device__ int   d_pos[T_TOK * TOPK];
__device__ float d_gbuf[(size_t)E_NUM * CAP * I_DIM];
__device__ float d_yb[(size_t)E_NUM * CAP * H_DIM];
__device__ float d_s1[(size_t)T_TOK * IS_DIM];
__device__ float d_s2[(size_t)T_TOK * H_DIM];

// ---------------- helpers ----------------
__device__ __forceinline__ unsigned tf32r(float x) {
    unsigned r;
    asm("cvt.rna.tf32.f32 %0, %1;" : "=r"(r) : "f"(x));
    return r;
}

__device__ __forceinline__ void mma8(float* c, unsigned a0, unsigned a1, unsigned a2,
                                     unsigned a3, unsigned b0, unsigned b1) {
    asm volatile(
        "mma.sync.aligned.m16n8k8.row.col.f32.tf32.tf32.f32 "
        "{%0,%1,%2,%3}, {%4,%5,%6,%7}, {%8,%9}, {%0,%1,%2,%3};"
        : "+f"(c[0]), "+f"(c[1]), "+f"(c[2]), "+f"(c[3])
        : "r"(a0), "r"(a1), "r"(a2), "r"(a3), "r"(b0), "r"(b1));
}

__device__ __forceinline__ void cp16(void* smem_dst, const void* gsrc) {
    unsigned d = (unsigned)__cvta_generic_to_shared(smem_dst);
    asm volatile("cp.async.ca.shared.global [%0], [%1], 16;" :: "r"(d), "l"(gsrc));
}
__device__ __forceinline__ void cp_commit() { asm volatile("cp.async.commit_group;"); }
__device__ __forceinline__ void cp_wait1()  { asm volatile("cp.async.wait_group 1;"); }

// ---------------- router: logits, top-8, softmax, shared gate ----------------
__global__ void router_kernel(const float* __restrict__ x,
                              const float* __restrict__ gw,
                              const float* __restrict__ wsg) {
    int t = blockIdx.x;
    __shared__ float xs[H_DIM];
    __shared__ float logits[E_NUM + 1];
    const float4* xr = (const float4*)(x + (size_t)t * H_DIM);
    for (int i = threadIdx.x; i < H_DIM / 4; i += blockDim.x)
        ((float4*)xs)[i] = xr[i];
    __syncthreads();
    int warp = threadIdx.x >> 5, lane = threadIdx.x & 31;
    for (int u = warp; u < E_NUM + 1; u += 8) {
        const float4* wrow = (const float4*)((u < E_NUM) ? (gw + (size_t)u * H_DIM) : wsg);
        float s = 0.f;
        for (int i = lane; i < H_DIM / 4; i += 32) {
            float4 a = ((const float4*)xs)[i];
            float4 b = wrow[i];
            s += a.x * b.x + a.y * b.y + a.z * b.z + a.w * b.w;
        }
        #pragma unroll
        for (int o = 16; o; o >>= 1) s += __shfl_xor_sync(0xffffffffu, s, o);
        if (lane == 0) logits[u] = s;
    }
    __syncthreads();
    if (threadIdx.x == 0) {
        unsigned long long used = 0ull;
        float vals[TOPK]; int idx[TOPK];
        for (int k = 0; k < TOPK; k++) {
            float best = -INFINITY; int bi = 0;
            for (int e = 0; e < E_NUM; e++)
                if (!((used >> e) & 1ull) && logits[e] > best) { best = logits[e]; bi = e; }
            used |= 1ull << bi; vals[k] = best; idx[k] = bi;
        }
        float m = vals[0], sum = 0.f, w[TOPK];
        for (int k = 0; k < TOPK; k++) { w[k] = expf(vals[k] - m); sum += w[k]; }
        float inv = 1.f / sum;
        for (int k = 0; k < TOPK; k++) {
            d_topk_w[t * TOPK + k]  = w[k] * inv;
            d_topk_idx[t * TOPK + k] = idx[k];
        }
        d_sgate[t] = logits[E_NUM];
    }
}

// ------- dispatch: stable rank within expert over flat (token,slot) order -------
__global__ void dispatch_kernel() {
    int e = blockIdx.x;
    __shared__ int warp_sums[8];
    __shared__ int base_s;
    if (threadIdx.x == 0) base_s = 0;
    int lane = threadIdx.x & 31, warp = threadIdx.x >> 5;
    for (int c = 0; c < T_TOK * TOPK; c += 256) {
        __syncthreads();
        int i = c + threadIdx.x;
        bool m = (d_topk_idx[i] == e);
        unsigned mask = __ballot_sync(0xffffffffu, m);
        if (lane == 0) warp_sums[warp] = __popc(mask);
        __syncthreads();
        int off = 0, total = 0;
        #pragma unroll
        for (int w = 0; w < 8; w++) { int v = warp_sums[w]; total += v; if (w < warp) off += v; }
        if (m) {
            int pos = base_s + off + __popc(mask & ((1u << lane) - 1u));
            d_pos[i] = pos;
            if (pos < CAP) d_toklist[e * CAP + pos] = i >> 3;
        }
        __syncthreads();
        if (threadIdx.x == 0) base_s += total;
    }
    __syncthreads();
    if (threadIdx.x == 0) d_cnt[e] = min(base_s, CAP);
}

// ---------------- dual GEMM (C1=A@B1, C3=A@B3) + SwiGLU epilogue ----------------
// 256 threads, 8 warps (4m x 2n), block tile 128x64 (per matrix), warp tile 32x32.
#define BM 128
#define BKx 32
#define ASTR 36
#define BSTR_D 72
#define SMEM_DUAL ((2 * BM * ASTR + 2 * 2 * BKx * BSTR_D) * 4)

__global__ void __launch_bounds__(256, 2)
dual_gemm_silu(const float* __restrict__ A, int lda, size_t strideA,
               const int* __restrict__ gather, const int* __restrict__ cnt,
               int mfull, int mtiles,
               const float* __restrict__ B1g, const float* __restrict__ B3g,
               int ldb, size_t strideB,
               float* __restrict__ Out, int ldo, size_t strideOut, int K) {
    extern __shared__ float sm[];
    float* As  = sm;                       // 2 * 128 * 36
    float* B1s = sm + 2 * BM * ASTR;       // 2 * 32 * 72
    float* B3s = B1s + 2 * BKx * BSTR_D;   // 2 * 32 * 72

    int e = blockIdx.x / mtiles;
    int mt = blockIdx.x - e * mtiles;
    int noff = blockIdx.y * 64;
    int nrows = cnt ? (cnt[e] - mt * BM) : (mfull - mt * BM);
    if (nrows <= 0) return;
    int valid = min(BM, nrows);

    int tid = threadIdx.x;
    int acol = (tid & 7) * 4;
    int arow0 = tid >> 3;                  // 0..31
    const float* aptr[4];
    #pragma unroll
    for (int i = 0; i < 4; i++) {
        int r = arow0 + i * 32;
        int rr = min(r, valid - 1);
        long grow = gather ? (long)gather[e * CAP + mt * BM + rr] : ((long)mt * BM + rr);
        aptr[i] = A + (size_t)e * strideA + (size_t)grow * lda + acol;
    }
    const float* b1ptr[2];
    const float* b3ptr[2];
    {
        const float* B1 = B1g + (size_t)e * strideB + noff;
        const float* B3 = B3g + (size_t)e * strideB + noff;
        #pragma unroll
        for (int i = 0; i < 2; i++) {
            int slot = tid + i * 256;
            int k = slot >> 4;             // 0..31
            int n4 = (slot & 15) * 4;      // 0..60
            b1ptr[i] = B1 + (size_t)k * ldb + n4;
            b3ptr[i] = B3 + (size_t)k * ldb + n4;
        }
    }

    float c1[2][4][4], c3[2][4][4];
    #pragma unroll
    for (int a = 0; a < 2; a++)
        #pragma unroll
        for (int b = 0; b < 4; b++)
            #pragma unroll
            for (int r = 0; r < 4; r++) { c1[a][b][r] = 0.f; c3[a][b][r] = 0.f; }

    int warp = tid >> 5, lane = tid & 31;
    int wm = warp & 3, wn = warp >> 2;     // 4m x 2n
    int g = lane >> 2, t4 = lane & 3;

    auto issue = [&](int s) {
        float* as = As + s * BM * ASTR;
        #pragma unroll
        for (int i = 0; i < 4; i++) {
            int r = arow0 + i * 32;
            cp16(as + r * ASTR + acol, aptr[i]);
            aptr[i] += BKx;
        }
        float* b1s = B1s + s * BKx * BSTR_D;
        float* b3s = B3s + s * BKx * BSTR_D;
        #pragma unroll
        for (int i = 0; i < 2; i++) {
            int slot = tid + i * 256;
            int k = slot >> 4;
            int n4 = (slot & 15) * 4;
            cp16(b1s + k * BSTR_D + n4, b1ptr[i]);
            cp16(b3s + k * BSTR_D + n4, b3ptr[i]);
            b1ptr[i] += (size_t)BKx * ldb;
            b3ptr[i] += (size_t)BKx * ldb;
        }
    };

    issue(0); cp_commit();
    int nk = K / BKx;
    for (int kb = 0; kb < nk; kb++) {
        int s = kb & 1;
        if (kb + 1 < nk) issue(s ^ 1);
        cp_commit();
        cp_wait1();
        __syncthreads();
        const float* as  = As + s * BM * ASTR;
        const float* b1s = B1s + s * BKx * BSTR_D;
        const float* b3s = B3s + s * BKx * BSTR_D;
        #pragma unroll
        for (int kk = 0; kk < 4; kk++) {
            int kc = kk * 8 + t4;
            unsigned af[2][4];
            #pragma unroll
            for (int mf = 0; mf < 2; mf++) {
                int r0 = wm * 32 + mf * 16 + g;
                af[mf][0] = tf32r(as[r0 * ASTR + kc]);
                af[mf][1] = tf32r(as[(r0 + 8) * ASTR + kc]);
                af[mf][2] = tf32r(as[r0 * ASTR + kc + 4]);
                af[mf][3] = tf32r(as[(r0 + 8) * ASTR + kc + 4]);
            }
            unsigned bf1[4][2], bf3[4][2];
            #pragma unroll
            for (int nf = 0; nf < 4; nf++) {
                int nn = wn * 32 + nf * 8 + g;
                bf1[nf][0] = tf32r(b1s[kc * BSTR_D + nn]);
                bf1[nf][1] = tf32r(b1s[(kc + 4) * BSTR_D + nn]);
                bf3[nf][0] = tf32r(b3s[kc * BSTR_D + nn]);
                bf3[nf][1] = tf32r(b3s[(kc + 4) * BSTR_D + nn]);
            }
            #pragma unroll
            for (int mf = 0; mf < 2; mf++)
                #pragma unroll
                for (int nf = 0; nf < 4; nf++) {
                    mma8(c1[mf][nf], af[mf][0], af[mf][1], af[mf][2], af[mf][3], bf1[nf][0], bf1[nf][1]);
                    mma8(c3[mf][nf], af[mf][0], af[mf][1], af[mf][2], af[mf][3], bf3[nf][0], bf3[nf][1]);
                }
        }
        __syncthreads();
    }

    float* outp = Out + (size_t)e * strideOut + (size_t)mt * BM * ldo + noff;
    #pragma unroll
    for (int mf = 0; mf < 2; mf++)
        #pragma unroll
        for (int nf = 0; nf < 4; nf++) {
            int r0 = wm * 32 + mf * 16 + g;
            int cc = wn * 32 + nf * 8 + t4 * 2;
            #pragma unroll
            for (int h = 0; h < 2; h++) {
                int r = r0 + h * 8;
                if (r < valid) {
                    float v1a = c1[mf][nf][h * 2 + 0], v3a = c3[mf][nf][h * 2 + 0];
                    float v1b = c1[mf][nf][h * 2 + 1], v3b = c3[mf][nf][h * 2 + 1];
                    float ga = (v1a / (1.f + expf(-v1a))) * v3a;
                    float gb = (v1b / (1.f + expf(-v1b))) * v3b;
                    *(float2*)(outp + (size_t)r * ldo + cc) = make_float2(ga, gb);
                }
            }
        }
}

// ---------------- single GEMM (C = A @ B) ----------------
// 256 threads, 8 warps (4m x 2n), block tile 128x128, warp tile 32x64.
#define BSTR_S 136
#define SMEM_SINGLE ((2 * BM * ASTR + 2 * BKx * BSTR_S) * 4)

__global__ void __launch_bounds__(256, 2)
single_gemm(const float* __restrict__ A, int lda, size_t strideA,
            const int* __restrict__ cnt, int mfull, int mtiles,
            const float* __restrict__ Bg, int ldb, size_t strideB,
            float* __restrict__ Out, int ldo, size_t strideOut, int K) {
    extern __shared__ float sm[];
    float* As = sm;                      // 2 * 128 * 36
    float* Bs = sm + 2 * BM * ASTR;      // 2 * 32 * 136

    int e = blockIdx.x / mtiles;
    int mt = blockIdx.x - e * mtiles;
    int noff = blockIdx.y * 128;
    int nrows = cnt ? (cnt[e] - mt * BM) : (mfull - mt * BM);
    if (nrows <= 0) return;
    int valid = min(BM, nrows);

    int tid = threadIdx.x;
    int acol = (tid & 7) * 4;
    int arow0 = tid >> 3;                // 0..31
    const float* aptr[4];
    #pragma unroll
    for (int i = 0; i < 4; i++) {
        int r = arow0 + i * 32;
        int rr = min(r, valid - 1);
        aptr[i] = A + (size_t)e * strideA + ((size_t)mt * BM + rr) * lda + acol;
    }
    const float* bptr[4];
    {
        const float* B = Bg + (size_t)e * strideB + noff;
        #pragma unroll
        for (int i = 0; i < 4; i++) {
            int slot = tid + i * 256;
            int k = slot >> 5;           // 0..31
            int n4 = (slot & 31) * 4;    // 0..124
            bptr[i] = B + (size_t)k * ldb + n4;
        }
    }

    float c[2][8][4];
    #pragma unroll
    for (int a = 0; a < 2; a++)
        #pragma unroll
        for (int b = 0; b < 8; b++)
            #pragma unroll
            for (int r = 0; r < 4; r++) c[a][b][r] = 0.f;

    int warp = tid >> 5, lane = tid & 31;
    int wm = warp & 3, wn = warp >> 2;   // 4m x 2n
    int g = lane >> 2, t4 = lane & 3;

    auto issue = [&](int s) {
        float* as = As + s * BM * ASTR;
        #pragma unroll
        for (int i = 0; i < 4; i++) {
            int r = arow0 + i * 32;
            cp16(as + r * ASTR + acol, aptr[i]);
            aptr[i] += BKx;
        }
        float* bs = Bs + s * BKx * BSTR_S;
        #pragma unroll
        for (int i = 0; i < 4; i++) {
            int slot = tid + i * 256;
            int k = slot >> 5;
            int n4 = (slot & 31) * 4;
            cp16(bs + k * BSTR_S + n4, bptr[i]);
            bptr[i] += (size_t)BKx * ldb;
        }
    };

    issue(0); cp_commit();
    int nk = K / BKx;
    for (int kb = 0; kb < nk; kb++) {
        int s = kb & 1;
        if (kb + 1 < nk) issue(s ^ 1);
        cp_commit();
        cp_wait1();
        __syncthreads();
        const float* as = As + s * BM * ASTR;
        const float* bs = Bs + s * BKx * BSTR_S;
        #pragma unroll
        for (int kk = 0; kk < 4; kk++) {
            int kc = kk * 8 + t4;
            unsigned af[2][4];
            #pragma unroll
            for (int mf = 0; mf < 2; mf++) {
                int r0 = wm * 32 + mf * 16 + g;
                af[mf][0] = tf32r(as[r0 * ASTR + kc]);
                af[mf][1] = tf32r(as[(r0 + 8) * ASTR + kc]);
                af[mf][2] = tf32r(as[r0 * ASTR + kc + 4]);
                af[mf][3] = tf32r(as[(r0 + 8) * ASTR + kc + 4]);
            }
            unsigned bf[8][2];
            #pragma unroll
            for (int nf = 0; nf < 8; nf++) {
                int nn = wn * 64 + nf * 8 + g;
                bf[nf][0] = tf32r(bs[kc * BSTR_S + nn]);
                bf[nf][1] = tf32r(bs[(kc + 4) * BSTR_S + nn]);
            }
            #pragma unroll
            for (int mf = 0; mf < 2; mf++)
                #pragma unroll
                for (int nf = 0; nf < 8; nf++)
                    mma8(c[mf][nf], af[mf][0], af[mf][1], af[mf][2], af[mf][3], bf[nf][0], bf[nf][1]);
        }
        __syncthreads();
    }

    float* outp = Out + (size_t)e * strideOut + (size_t)mt * BM * ldo + noff;
    #pragma unroll
    for (int mf = 0; mf < 2; mf++)
        #pragma unroll
        for (int nf = 0; nf < 8; nf++) {
            int r0 = wm * 32 + mf * 16 + g;
            int cc = wn * 64 + nf * 8 + t4 * 2;
            #pragma unroll
            for (int h = 0; h < 2; h++) {
                int r = r0 + h * 8;
                if (r < valid)
                    *(float2*)(outp + (size_t)r * ldo + cc) =
                        make_float2(c[mf][nf][h * 2 + 0], c[mf][nf][h * 2 + 1]);
            }
        }
}

// ---------------- combine: routed + sigmoid-gated shared ----------------
__global__ void combine_kernel(float* __restrict__ out) {
    int t = blockIdx.x;
    __shared__ int rows[TOPK];
    __shared__ float ws[TOPK];
    if (threadIdx.x < TOPK) {
        int k = threadIdx.x;
        int ee = d_topk_idx[t * TOPK + k];
        int p  = d_pos[t * TOPK + k];
        rows[k] = (p < CAP) ? (ee * CAP + p) : -1;
        ws[k] = d_topk_w[t * TOPK + k];
    }
    __syncthreads();
    float sg = 1.f / (1.f + expf(-d_sgate[t]));
    #pragma unroll
    for (int j = 0; j < 2; j++) {
        int h = threadIdx.x * 4 + j * 1024;
        float4 acc = *(const float4*)(d_s2 + (size_t)t * H_DIM + h);
        acc.x *= sg; acc.y *= sg; acc.z *= sg; acc.w *= sg;
        #pragma unroll
        for (int k = 0; k < TOPK; k++) {
            int r = rows[k];
            if (r >= 0) {
                float w = ws[k];
                float4 y = *(const float4*)(d_yb + (size_t)r * H_DIM + h);
                acc.x += w * y.x; acc.y += w * y.y; acc.z += w * y.z; acc.w += w * y.w;
            }
        }
        *(float4*)(out + (size_t)t * H_DIM + h) = acc;
    }
}

// ---------------- launch ----------------
extern "C" void kernel_launch(void* const* d_in, const int* in_sizes, int n_in,
                              void* d_out, int out_size) {
    (void)in_sizes; (void)n_in; (void)out_size;
    const float* x   = (const float*)d_in[0];
    const float* gw  = (const float*)d_in[1];
    const float* w1  = (const float*)d_in[2];
    const float* w3  = (const float*)d_in[3];
    const float* w2  = (const float*)d_in[4];
    const float* ws1 = (const float*)d_in[5];
    const float* ws3 = (const float*)d_in[6];
    const float* ws2 = (const float*)d_in[7];
    const float* wsg = (const float*)d_in[8];
    float* out = (float*)d_out;

    // one-time resources (not device memory; work per call is identical)
    static cudaStream_t sB = nullptr;
    static cudaEvent_t evFork = nullptr, evJoin = nullptr;
    if (sB == nullptr) {
        cudaStreamCreateWithFlags(&sB, cudaStreamNonBlocking);
        cudaEventCreateWithFlags(&evFork, cudaEventDisableTiming);
        cudaEventCreateWithFlags(&evJoin, cudaEventDisableTiming);
    }

    cudaFuncSetAttribute(dual_gemm_silu, cudaFuncAttributeMaxDynamicSharedMemorySize, SMEM_DUAL);
    cudaFuncSetAttribute(single_gemm,    cudaFuncAttributeMaxDynamicSharedMemorySize, SMEM_SINGLE);

    float *gbuf, *yb, *s1, *s2;
    int *cnt, *toklist;
    cudaGetSymbolAddress((void**)&gbuf, d_gbuf);
    cudaGetSymbolAddress((void**)&yb, d_yb);
    cudaGetSymbolAddress((void**)&s1, d_s1);
    cudaGetSymbolAddress((void**)&s2, d_s2);
    cudaGetSymbolAddress((void**)&cnt, d_cnt);
    cudaGetSymbolAddress((void**)&toklist, d_toklist);

    // fork: shared-expert chain is independent of router/dispatch/experts
    cudaEventRecord(evFork, 0);
    cudaStreamWaitEvent(sB, evFork, 0);

    // ---- stream B: shared expert chain ----
    // shared: S1 = silu(X@ws1) * (X@ws3)
    dual_gemm_silu<<<dim3(8, IS_DIM / 64), 256, SMEM_DUAL, sB>>>(
        x, H_DIM, 0, nullptr, nullptr, T_TOK, 8,
        ws1, ws3, IS_DIM, 0,
        s1, IS_DIM, 0, H_DIM);
    // shared: S2 = S1 @ ws2
    single_gemm<<<dim3(8, H_DIM / 128), 256, SMEM_SINGLE, sB>>>(
        s1, IS_DIM, 0, nullptr, T_TOK, 8,
        ws2, H_DIM, 0,
        s2, H_DIM, 0, IS_DIM);
    cudaEventRecord(evJoin, sB);

    // ---- default stream: routed expert chain ----
    router_kernel<<<T_TOK, 256>>>(x, gw, wsg);
    dispatch_kernel<<<E_NUM, 256>>>();

    // experts: G = silu(X@w1) * (X@w3)   [gathered rows]
    dual_gemm_silu<<<dim3(E_NUM * 2, I_DIM / 64), 256, SMEM_DUAL>>>(
        x, H_DIM, 0, toklist, cnt, 0, 2,
        w1, w3, I_DIM, (size_t)H_DIM * I_DIM,
        gbuf, I_DIM, (size_t)CAP * I_DIM, H_DIM);

    // experts: Y = G @ w2
    single_gemm<<<dim3(E_NUM * 2, H_DIM / 128), 256, SMEM_SINGLE>>>(
        gbuf, I_DIM, (size_t)CAP * I_DIM, cnt, 0, 2,
        w2, H_DIM, (size_t)I_DIM * H_DIM,
        yb, H_DIM, (size_t)CAP * H_DIM, I_DIM);

    // join: combine needs both chains
    cudaStreamWaitEvent(0, evJoin, 0);
    combine_kernel<<<T_TOK, 256>>>(out);
}

// round 10
// speedup vs baseline: 1.7738x; 1.0334x over previous
#include <cuda_runtime.h>
#include <cstdint>
#include <math.h>

#define T_TOK 1024
#define H_DIM 2048
#define E_NUM 64
#define I_DIM 512
#define IS_DIM 1024
#define TOPK 8
#define CAP 256

// ---------------- scratch (static device globals; no allocs) ----------------
__device__ int   d_topk_idx[T_TOK * TOPK];
__device__ float d_topk_w[T_TOK * TOPK];
__device__ float d_sgate[T_TOK];
__device__ int   d_cnt[E_NUM];
__device__ int   d_toklist[E_NUM * CAP];
__device__ int   d_pos[T_TOK * TOPK];
__device__ float d_gbuf[(size_t)E_NUM * CAP * I_DIM];
__device__ float d_yb[(size_t)E_NUM * CAP * H_DIM];
__device__ float d_s1[(size_t)T_TOK * IS_DIM];
__device__ float d_s2[(size_t)T_TOK * H_DIM];

// ---------------- helpers ----------------
__device__ __forceinline__ unsigned tf32r(float x) {
    unsigned r;
    asm("cvt.rna.tf32.f32 %0, %1;" : "=r"(r) : "f"(x));
    return r;
}

__device__ __forceinline__ void mma8(float* c, unsigned a0, unsigned a1, unsigned a2,
                                     unsigned a3, unsigned b0, unsigned b1) {
    asm volatile(
        "mma.sync.aligned.m16n8k8.row.col.f32.tf32.tf32.f32 "
        "{%0,%1,%2,%3}, {%4,%5,%6,%7}, {%8,%9}, {%0,%1,%2,%3};"
        : "+f"(c[0]), "+f"(c[1]), "+f"(c[2]), "+f"(c[3])
        : "r"(a0), "r"(a1), "r"(a2), "r"(a3), "r"(b0), "r"(b1));
}

__device__ __forceinline__ void cp16(void* smem_dst, const void* gsrc) {
    unsigned d = (unsigned)__cvta_generic_to_shared(smem_dst);
    asm volatile("cp.async.ca.shared.global [%0], [%1], 16;" :: "r"(d), "l"(gsrc));
}
__device__ __forceinline__ void cp_commit() { asm volatile("cp.async.commit_group;"); }
__device__ __forceinline__ void cp_wait1()  { asm volatile("cp.async.wait_group 1;"); }

// ---------------- router v2: 8 tokens/block, gw read once per block ----------------
// grid 128, block 256 (8 warps). Warp w owns k-slice [w*256, w*256+256).
// Per lane: 2 float4 of each of 8 tokens' x in registers. Loop 65 rows (64 experts
// + shared gate), butterfly-reduce, per-warp partials to smem, tree-reduce, top-8.
__global__ void __launch_bounds__(256)
router_kernel(const float* __restrict__ x,
              const float* __restrict__ gw,
              const float* __restrict__ wsg) {
    __shared__ float part[8][8 * 65];   // [warp][t*65+e]
    __shared__ float logits[8 * 65];    // [t*65+e]

    int tid = threadIdx.x, w = tid >> 5, lane = tid & 31;
    int t0 = blockIdx.x * 8;

    // x slices into registers: token t, f4 index w*64 + j*32 + lane
    float4 xr[8][2];
    #pragma unroll
    for (int t = 0; t < 8; t++) {
        const float4* xrow = (const float4*)(x + (size_t)(t0 + t) * H_DIM);
        #pragma unroll
        for (int j = 0; j < 2; j++)
            xr[t][j] = xrow[w * 64 + j * 32 + lane];
    }

    for (int e = 0; e < E_NUM + 1; e++) {
        const float4* wrow = (const float4*)((e < E_NUM) ? (gw + (size_t)e * H_DIM) : wsg);
        float4 wv0 = wrow[w * 64 + lane];
        float4 wv1 = wrow[w * 64 + 32 + lane];
        float acc[8];
        #pragma unroll
        for (int t = 0; t < 8; t++) {
            acc[t] = xr[t][0].x * wv0.x + xr[t][0].y * wv0.y +
                     xr[t][0].z * wv0.z + xr[t][0].w * wv0.w +
                     xr[t][1].x * wv1.x + xr[t][1].y * wv1.y +
                     xr[t][1].z * wv1.z + xr[t][1].w * wv1.w;
        }
        #pragma unroll
        for (int o = 16; o; o >>= 1)
            #pragma unroll
            for (int t = 0; t < 8; t++)
                acc[t] += __shfl_xor_sync(0xffffffffu, acc[t], o);
        if (lane < 8) part[w][lane * 65 + e] = acc[lane];
    }
    __syncthreads();

    // tree-reduce 8 warps' partials (fixed order -> deterministic)
    for (int idx = tid; idx < 8 * 65; idx += 256) {
        float s = 0.f;
        #pragma unroll
        for (int ww = 0; ww < 8; ww++) s += part[ww][idx];
        logits[idx] = s;
    }
    __syncthreads();

    // top-8 + renormalized softmax (thread t handles token t0+t)
    if (tid < 8) {
        const float* lg = logits + tid * 65;
        int t = t0 + tid;
        unsigned long long used = 0ull;
        float vals[TOPK]; int idx[TOPK];
        for (int k = 0; k < TOPK; k++) {
            float best = -INFINITY; int bi = 0;
            for (int e = 0; e < E_NUM; e++)
                if (!((used >> e) & 1ull) && lg[e] > best) { best = lg[e]; bi = e; }
            used |= 1ull << bi; vals[k] = best; idx[k] = bi;
        }
        float m = vals[0], sum = 0.f, wgt[TOPK];
        for (int k = 0; k < TOPK; k++) { wgt[k] = expf(vals[k] - m); sum += wgt[k]; }
        float inv = 1.f / sum;
        for (int k = 0; k < TOPK; k++) {
            d_topk_w[t * TOPK + k]  = wgt[k] * inv;
            d_topk_idx[t * TOPK + k] = idx[k];
        }
        d_sgate[t] = lg[E_NUM];
    }
}

// ------- dispatch v2: single block, match_any + cross-warp scan, stable ranks -------
__global__ void __launch_bounds__(1024)
dispatch_kernel() {
    __shared__ int wcnt[32][64];   // per-warp per-expert counts (this round)
    __shared__ int woff[32][64];   // exclusive prefix across warps
    __shared__ int base[64];       // running per-expert global base

    int tid = threadIdx.x, w = tid >> 5, lane = tid & 31;
    if (tid < 64) base[tid] = 0;
    int myrun = 0;                 // valid for tid < 64 inside loop

    for (int r = 0; r < 8; r++) {
        int i = r * 1024 + tid;
        int e = d_topk_idx[i];
        unsigned mask = __match_any_sync(0xffffffffu, e);
        int lr = __popc(mask & ((1u << lane) - 1u));
        bool leader = ((__ffs(mask) - 1) == lane);

        // zero counts (2048 ints / 1024 threads)
        ((int*)wcnt)[tid * 2]     = 0;
        ((int*)wcnt)[tid * 2 + 1] = 0;
        __syncthreads();
        if (leader) wcnt[w][e] = __popc(mask);
        __syncthreads();
        if (tid < 64) {
            int run = 0;
            #pragma unroll
            for (int ww = 0; ww < 32; ww++) { woff[ww][tid] = run; run += wcnt[ww][tid]; }
            myrun = run;
        }
        __syncthreads();
        int pos = base[e] + woff[w][e] + lr;
        d_pos[i] = pos;
        if (pos < CAP) d_toklist[e * CAP + pos] = i >> 3;
        __syncthreads();
        if (tid < 64) base[tid] += myrun;
        __syncthreads();
    }
    if (tid < 64) d_cnt[tid] = min(base[tid], CAP);
}

// ---------------- dual GEMM (C1=A@B1, C3=A@B3) + SwiGLU epilogue ----------------
// 256 threads, 8 warps (4m x 2n), block tile 128x64 (per matrix), warp tile 32x32.
#define BM 128
#define BKx 32
#define ASTR 36
#define BSTR_D 72
#define SMEM_DUAL ((2 * BM * ASTR + 2 * 2 * BKx * BSTR_D) * 4)

__global__ void __launch_bounds__(256, 2)
dual_gemm_silu(const float* __restrict__ A, int lda, size_t strideA,
               const int* __restrict__ gather, const int* __restrict__ cnt,
               int mfull, int mtiles,
               const float* __restrict__ B1g, const float* __restrict__ B3g,
               int ldb, size_t strideB,
               float* __restrict__ Out, int ldo, size_t strideOut, int K) {
    extern __shared__ float sm[];
    float* As  = sm;                       // 2 * 128 * 36
    float* B1s = sm + 2 * BM * ASTR;       // 2 * 32 * 72
    float* B3s = B1s + 2 * BKx * BSTR_D;   // 2 * 32 * 72

    int e = blockIdx.x / mtiles;
    int mt = blockIdx.x - e * mtiles;
    int noff = blockIdx.y * 64;
    int nrows = cnt ? (cnt[e] - mt * BM) : (mfull - mt * BM);
    if (nrows <= 0) return;
    int valid = min(BM, nrows);

    int tid = threadIdx.x;
    int acol = (tid & 7) * 4;
    int arow0 = tid >> 3;                  // 0..31
    const float* aptr[4];
    #pragma unroll
    for (int i = 0; i < 4; i++) {
        int r = arow0 + i * 32;
        int rr = min(r, valid - 1);
        long grow = gather ? (long)gather[e * CAP + mt * BM + rr] : ((long)mt * BM + rr);
        aptr[i] = A + (size_t)e * strideA + (size_t)grow * lda + acol;
    }
    const float* b1ptr[2];
    const float* b3ptr[2];
    {
        const float* B1 = B1g + (size_t)e * strideB + noff;
        const float* B3 = B3g + (size_t)e * strideB + noff;
        #pragma unroll
        for (int i = 0; i < 2; i++) {
            int slot = tid + i * 256;
            int k = slot >> 4;             // 0..31
            int n4 = (slot & 15) * 4;      // 0..60
            b1ptr[i] = B1 + (size_t)k * ldb + n4;
            b3ptr[i] = B3 + (size_t)k * ldb + n4;
        }
    }

    float c1[2][4][4], c3[2][4][4];
    #pragma unroll
    for (int a = 0; a < 2; a++)
        #pragma unroll
        for (int b = 0; b < 4; b++)
            #pragma unroll
            for (int r = 0; r < 4; r++) { c1[a][b][r] = 0.f; c3[a][b][r] = 0.f; }

    int warp = tid >> 5, lane = tid & 31;
    int wm = warp & 3, wn = warp >> 2;     // 4m x 2n
    int g = lane >> 2, t4 = lane & 3;

    auto issue = [&](int s) {
        float* as = As + s * BM * ASTR;
        #pragma unroll
        for (int i = 0; i < 4; i++) {
            int r = arow0 + i * 32;
            cp16(as + r * ASTR + acol, aptr[i]);
            aptr[i] += BKx;
        }
        float* b1s = B1s + s * BKx * BSTR_D;
        float* b3s = B3s + s * BKx * BSTR_D;
        #pragma unroll
        for (int i = 0; i < 2; i++) {
            int slot = tid + i * 256;
            int k = slot >> 4;
            int n4 = (slot & 15) * 4;
            cp16(b1s + k * BSTR_D + n4, b1ptr[i]);
            cp16(b3s + k * BSTR_D + n4, b3ptr[i]);
            b1ptr[i] += (size_t)BKx * ldb;
            b3ptr[i] += (size_t)BKx * ldb;
        }
    };

    issue(0); cp_commit();
    int nk = K / BKx;
    for (int kb = 0; kb < nk; kb++) {
        int s = kb & 1;
        if (kb + 1 < nk) issue(s ^ 1);
        cp_commit();
        cp_wait1();
        __syncthreads();
        const float* as  = As + s * BM * ASTR;
        const float* b1s = B1s + s * BKx * BSTR_D;
        const float* b3s = B3s + s * BKx * BSTR_D;
        #pragma unroll
        for (int kk = 0; kk < 4; kk++) {
            int kc = kk * 8 + t4;
            unsigned af[2][4];
            #pragma unroll
            for (int mf = 0; mf < 2; mf++) {
                int r0 = wm * 32 + mf * 16 + g;
                af[mf][0] = tf32r(as[r0 * ASTR + kc]);
                af[mf][1] = tf32r(as[(r0 + 8) * ASTR + kc]);
                af[mf][2] = tf32r(as[r0 * ASTR + kc + 4]);
                af[mf][3] = tf32r(as[(r0 + 8) * ASTR + kc + 4]);
            }
            unsigned bf1[4][2], bf3[4][2];
            #pragma unroll
            for (int nf = 0; nf < 4; nf++) {
                int nn = wn * 32 + nf * 8 + g;
                bf1[nf][0] = tf32r(b1s[kc * BSTR_D + nn]);
                bf1[nf][1] = tf32r(b1s[(kc + 4) * BSTR_D + nn]);
                bf3[nf][0] = tf32r(b3s[kc * BSTR_D + nn]);
                bf3[nf][1] = tf32r(b3s[(kc + 4) * BSTR_D + nn]);
            }
            #pragma unroll
            for (int mf = 0; mf < 2; mf++)
                #pragma unroll
                for (int nf = 0; nf < 4; nf++) {
                    mma8(c1[mf][nf], af[mf][0], af[mf][1], af[mf][2], af[mf][3], bf1[nf][0], bf1[nf][1]);
                    mma8(c3[mf][nf], af[mf][0], af[mf][1], af[mf][2], af[mf][3], bf3[nf][0], bf3[nf][1]);
                }
        }
        __syncthreads();
    }

    float* outp = Out + (size_t)e * strideOut + (size_t)mt * BM * ldo + noff;
    #pragma unroll
    for (int mf = 0; mf < 2; mf++)
        #pragma unroll
        for (int nf = 0; nf < 4; nf++) {
            int r0 = wm * 32 + mf * 16 + g;
            int cc = wn * 32 + nf * 8 + t4 * 2;
            #pragma unroll
            for (int h = 0; h < 2; h++) {
                int r = r0 + h * 8;
                if (r < valid) {
                    float v1a = c1[mf][nf][h * 2 + 0], v3a = c3[mf][nf][h * 2 + 0];
                    float v1b = c1[mf][nf][h * 2 + 1], v3b = c3[mf][nf][h * 2 + 1];
                    float ga = (v1a / (1.f + expf(-v1a))) * v3a;
                    float gb = (v1b / (1.f + expf(-v1b))) * v3b;
                    *(float2*)(outp + (size_t)r * ldo + cc) = make_float2(ga, gb);
                }
            }
        }
}

// ---------------- single GEMM (C = A @ B) ----------------
// 256 threads, 8 warps (4m x 2n), block tile 128x128, warp tile 32x64.
#define BSTR_S 136
#define SMEM_SINGLE ((2 * BM * ASTR + 2 * BKx * BSTR_S) * 4)

__global__ void __launch_bounds__(256, 2)
single_gemm(const float* __restrict__ A, int lda, size_t strideA,
            const int* __restrict__ cnt, int mfull, int mtiles,
            const float* __restrict__ Bg, int ldb, size_t strideB,
            float* __restrict__ Out, int ldo, size_t strideOut, int K) {
    extern __shared__ float sm[];
    float* As = sm;                      // 2 * 128 * 36
    float* Bs = sm + 2 * BM * ASTR;      // 2 * 32 * 136

    int e = blockIdx.x / mtiles;
    int mt = blockIdx.x - e * mtiles;
    int noff = blockIdx.y * 128;
    int nrows = cnt ? (cnt[e] - mt * BM) : (mfull - mt * BM);
    if (nrows <= 0) return;
    int valid = min(BM, nrows);

    int tid = threadIdx.x;
    int acol = (tid & 7) * 4;
    int arow0 = tid >> 3;                // 0..31
    const float* aptr[4];
    #pragma unroll
    for (int i = 0; i < 4; i++) {
        int r = arow0 + i * 32;
        int rr = min(r, valid - 1);
        aptr[i] = A + (size_t)e * strideA + ((size_t)mt * BM + rr) * lda + acol;
    }
    const float* bptr[4];
    {
        const float* B = Bg + (size_t)e * strideB + noff;
        #pragma unroll
        for (int i = 0; i < 4; i++) {
            int slot = tid + i * 256;
            int k = slot >> 5;           // 0..31
            int n4 = (slot & 31) * 4;    // 0..124
            bptr[i] = B + (size_t)k * ldb + n4;
        }
    }

    float c[2][8][4];
    #pragma unroll
    for (int a = 0; a < 2; a++)
        #pragma unroll
        for (int b = 0; b < 8; b++)
            #pragma unroll
            for (int r = 0; r < 4; r++) c[a][b][r] = 0.f;

    int warp = tid >> 5, lane = tid & 31;
    int wm = warp & 3, wn = warp >> 2;   // 4m x 2n
    int g = lane >> 2, t4 = lane & 3;

    auto issue = [&](int s) {
        float* as = As + s * BM * ASTR;
        #pragma unroll
        for (int i = 0; i < 4; i++) {
            int r = arow0 + i * 32;
            cp16(as + r * ASTR + acol, aptr[i]);
            aptr[i] += BKx;
        }
        float* bs = Bs + s * BKx * BSTR_S;
        #pragma unroll
        for (int i = 0; i < 4; i++) {
            int slot = tid + i * 256;
            int k = slot >> 5;
            int n4 = (slot & 31) * 4;
            cp16(bs + k * BSTR_S + n4, bptr[i]);
            bptr[i] += (size_t)BKx * ldb;
        }
    };

    issue(0); cp_commit();
    int nk = K / BKx;
    for (int kb = 0; kb < nk; kb++) {
        int s = kb & 1;
        if (kb + 1 < nk) issue(s ^ 1);
        cp_commit();
        cp_wait1();
        __syncthreads();
        const float* as = As + s * BM * ASTR;
        const float* bs = Bs + s * BKx * BSTR_S;
        #pragma unroll
        for (int kk = 0; kk < 4; kk++) {
            int kc = kk * 8 + t4;
            unsigned af[2][4];
            #pragma unroll
            for (int mf = 0; mf < 2; mf++) {
                int r0 = wm * 32 + mf * 16 + g;
                af[mf][0] = tf32r(as[r0 * ASTR + kc]);
                af[mf][1] = tf32r(as[(r0 + 8) * ASTR + kc]);
                af[mf][2] = tf32r(as[r0 * ASTR + kc + 4]);
                af[mf][3] = tf32r(as[(r0 + 8) * ASTR + kc + 4]);
            }
            unsigned bf[8][2];
            #pragma unroll
            for (int nf = 0; nf < 8; nf++) {
                int nn = wn * 64 + nf * 8 + g;
                bf[nf][0] = tf32r(bs[kc * BSTR_S + nn]);
                bf[nf][1] = tf32r(bs[(kc + 4) * BSTR_S + nn]);
            }
            #pragma unroll
            for (int mf = 0; mf < 2; mf++)
                #pragma unroll
                for (int nf = 0; nf < 8; nf++)
                    mma8(c[mf][nf], af[mf][0], af[mf][1], af[mf][2], af[mf][3], bf[nf][0], bf[nf][1]);
        }
        __syncthreads();
    }

    float* outp = Out + (size_t)e * strideOut + (size_t)mt * BM * ldo + noff;
    #pragma unroll
    for (int mf = 0; mf < 2; mf++)
        #pragma unroll
        for (int nf = 0; nf < 8; nf++) {
            int r0 = wm * 32 + mf * 16 + g;
            int cc = wn * 64 + nf * 8 + t4 * 2;
            #pragma unroll
            for (int h = 0; h < 2; h++) {
                int r = r0 + h * 8;
                if (r < valid)
                    *(float2*)(outp + (size_t)r * ldo + cc) =
                        make_float2(c[mf][nf][h * 2 + 0], c[mf][nf][h * 2 + 1]);
            }
        }
}

// ---------------- combine: routed + sigmoid-gated shared ----------------
__global__ void combine_kernel(float* __restrict__ out) {
    int t = blockIdx.x;
    __shared__ int rows[TOPK];
    __shared__ float ws[TOPK];
    if (threadIdx.x < TOPK) {
        int k = threadIdx.x;
        int ee = d_topk_idx[t * TOPK + k];
        int p  = d_pos[t * TOPK + k];
        rows[k] = (p < CAP) ? (ee * CAP + p) : -1;
        ws[k] = d_topk_w[t * TOPK + k];
    }
    __syncthreads();
    float sg = 1.f / (1.f + expf(-d_sgate[t]));
    #pragma unroll
    for (int j = 0; j < 2; j++) {
        int h = threadIdx.x * 4 + j * 1024;
        float4 acc = *(const float4*)(d_s2 + (size_t)t * H_DIM + h);
        acc.x *= sg; acc.y *= sg; acc.z *= sg; acc.w *= sg;
        #pragma unroll
        for (int k = 0; k < TOPK; k++) {
            int r = rows[k];
            if (r >= 0) {
                float w = ws[k];
                float4 y = *(const float4*)(d_yb + (size_t)r * H_DIM + h);
                acc.x += w * y.x; acc.y += w * y.y; acc.z += w * y.z; acc.w += w * y.w;
            }
        }
        *(float4*)(out + (size_t)t * H_DIM + h) = acc;
    }
}

// ---------------- launch ----------------
extern "C" void kernel_launch(void* const* d_in, const int* in_sizes, int n_in,
                              void* d_out, int out_size) {
    (void)in_sizes; (void)n_in; (void)out_size;
    const float* x   = (const float*)d_in[0];
    const float* gw  = (const float*)d_in[1];
    const float* w1  = (const float*)d_in[2];
    const float* w3  = (const float*)d_in[3];
    const float* w2  = (const float*)d_in[4];
    const float* ws1 = (const float*)d_in[5];
    const float* ws3 = (const float*)d_in[6];
    const float* ws2 = (const float*)d_in[7];
    const float* wsg = (const float*)d_in[8];
    float* out = (float*)d_out;

    // one-time resources (not device memory; work per call is identical)
    static cudaStream_t sB = nullptr;
    static cudaEvent_t evFork = nullptr, evJoin = nullptr;
    if (sB == nullptr) {
        cudaStreamCreateWithFlags(&sB, cudaStreamNonBlocking);
        cudaEventCreateWithFlags(&evFork, cudaEventDisableTiming);
        cudaEventCreateWithFlags(&evJoin, cudaEventDisableTiming);
    }

    cudaFuncSetAttribute(dual_gemm_silu, cudaFuncAttributeMaxDynamicSharedMemorySize, SMEM_DUAL);
    cudaFuncSetAttribute(single_gemm,    cudaFuncAttributeMaxDynamicSharedMemorySize, SMEM_SINGLE);

    float *gbuf, *yb, *s1, *s2;
    int *cnt, *toklist;
    cudaGetSymbolAddress((void**)&gbuf, d_gbuf);
    cudaGetSymbolAddress((void**)&yb, d_yb);
    cudaGetSymbolAddress((void**)&s1, d_s1);
    cudaGetSymbolAddress((void**)&s2, d_s2);
    cudaGetSymbolAddress((void**)&cnt, d_cnt);
    cudaGetSymbolAddress((void**)&toklist, d_toklist);

    // fork: shared-expert chain is independent of router/dispatch/experts
    cudaEventRecord(evFork, 0);
    cudaStreamWaitEvent(sB, evFork, 0);

    // ---- stream B: shared expert chain ----
    dual_gemm_silu<<<dim3(8, IS_DIM / 64), 256, SMEM_DUAL, sB>>>(
        x, H_DIM, 0, nullptr, nullptr, T_TOK, 8,
        ws1, ws3, IS_DIM, 0,
        s1, IS_DIM, 0, H_DIM);
    single_gemm<<<dim3(8, H_DIM / 128), 256, SMEM_SINGLE, sB>>>(
        s1, IS_DIM, 0, nullptr, T_TOK, 8,
        ws2, H_DIM, 0,
        s2, H_DIM, 0, IS_DIM);
    cudaEventRecord(evJoin, sB);

    // ---- default stream: routed expert chain ----
    router_kernel<<<T_TOK / 8, 256>>>(x, gw, wsg);
    dispatch_kernel<<<1, 1024>>>();

    // experts: G = silu(X@w1) * (X@w3)   [gathered rows]
    dual_gemm_silu<<<dim3(E_NUM * 2, I_DIM / 64), 256, SMEM_DUAL>>>(
        x, H_DIM, 0, toklist, cnt, 0, 2,
        w1, w3, I_DIM, (size_t)H_DIM * I_DIM,
        gbuf, I_DIM, (size_t)CAP * I_DIM, H_DIM);

    // experts: Y = G @ w2
    single_gemm<<<dim3(E_NUM * 2, H_DIM / 128), 256, SMEM_SINGLE>>>(
        gbuf, I_DIM, (size_t)CAP * I_DIM, cnt, 0, 2,
        w2, H_DIM, (size_t)I_DIM * H_DIM,
        yb, H_DIM, (size_t)CAP * H_DIM, I_DIM);

    // join: combine needs both chains
    cudaStreamWaitEvent(0, evJoin, 0);
    combine_kernel<<<T_TOK, 256>>>(out);
}

// round 11
// speedup vs baseline: 2.1443x; 1.2089x over previous
#include <cuda_runtime.h>
#include <cuda_fp16.h>
#include <cstdint>
#include <math.h>

#define T_TOK 1024
#define H_DIM 2048
#define E_NUM 64
#define I_DIM 512
#define IS_DIM 1024
#define TOPK 8
#define CAP 256

#define BKx 32
#define ASTRH 20            // half2 per A row (16 data + 4 pad)
#define BSTRH_D 72          // half2 per B k2-row (dual, 64 data + 8 pad)
#define BSTRH_S 136         // half2 per B k2-row (single, 128 data + 8 pad)
#define A_STG (128 * ASTRH)             // 2560 u32
#define BD_STG (16 * BSTRH_D)           // 1152 u32
#define BS_STG (16 * BSTRH_S)           // 2176 u32
#define SMEM_DUAL ((2 * A_STG + 2 * 2 * BD_STG) * 4)   // 38912 B
#define SMEM_SINGLE ((2 * A_STG + 2 * BS_STG) * 4)     // 37888 B

// ---------------- scratch (static device globals; no allocs) ----------------
__device__ int   d_topk_idx[T_TOK * TOPK];
__device__ float d_topk_w[T_TOK * TOPK];
__device__ float d_sgate[T_TOK];
__device__ int   d_cnt[E_NUM];
__device__ int   d_toklist[E_NUM * CAP];
__device__ int   d_pos[T_TOK * TOPK];
__device__ float d_gbuf[(size_t)E_NUM * CAP * I_DIM];
__device__ float d_yb[(size_t)E_NUM * CAP * H_DIM];
__device__ float d_s1[(size_t)T_TOK * IS_DIM];
__device__ float d_s2[(size_t)T_TOK * H_DIM];

// ---------------- helpers ----------------
__device__ __forceinline__ unsigned pack2(float x, float y) {
    __half2 h = __floats2half2_rn(x, y);   // .x = x (low), .y = y (high)
    return *reinterpret_cast<unsigned*>(&h);
}

__device__ __forceinline__ void mma16(float* c, const unsigned* a, unsigned b0, unsigned b1) {
    asm volatile(
        "mma.sync.aligned.m16n8k16.row.col.f32.f16.f16.f32 "
        "{%0,%1,%2,%3}, {%4,%5,%6,%7}, {%8,%9}, {%0,%1,%2,%3};"
        : "+f"(c[0]), "+f"(c[1]), "+f"(c[2]), "+f"(c[3])
        : "r"(a[0]), "r"(a[1]), "r"(a[2]), "r"(a[3]), "r"(b0), "r"(b1));
}

// ---------------- router v2: 8 tokens/block, gw read once per block ----------------
__global__ void __launch_bounds__(256)
router_kernel(const float* __restrict__ x,
              const float* __restrict__ gw,
              const float* __restrict__ wsg) {
    __shared__ float part[8][8 * 65];
    __shared__ float logits[8 * 65];

    int tid = threadIdx.x, w = tid >> 5, lane = tid & 31;
    int t0 = blockIdx.x * 8;

    float4 xr[8][2];
    #pragma unroll
    for (int t = 0; t < 8; t++) {
        const float4* xrow = (const float4*)(x + (size_t)(t0 + t) * H_DIM);
        #pragma unroll
        for (int j = 0; j < 2; j++)
            xr[t][j] = xrow[w * 64 + j * 32 + lane];
    }

    for (int e = 0; e < E_NUM + 1; e++) {
        const float4* wrow = (const float4*)((e < E_NUM) ? (gw + (size_t)e * H_DIM) : wsg);
        float4 wv0 = wrow[w * 64 + lane];
        float4 wv1 = wrow[w * 64 + 32 + lane];
        float acc[8];
        #pragma unroll
        for (int t = 0; t < 8; t++) {
            acc[t] = xr[t][0].x * wv0.x + xr[t][0].y * wv0.y +
                     xr[t][0].z * wv0.z + xr[t][0].w * wv0.w +
                     xr[t][1].x * wv1.x + xr[t][1].y * wv1.y +
                     xr[t][1].z * wv1.z + xr[t][1].w * wv1.w;
        }
        #pragma unroll
        for (int o = 16; o; o >>= 1)
            #pragma unroll
            for (int t = 0; t < 8; t++)
                acc[t] += __shfl_xor_sync(0xffffffffu, acc[t], o);
        if (lane < 8) part[w][lane * 65 + e] = acc[lane];
    }
    __syncthreads();

    for (int idx = tid; idx < 8 * 65; idx += 256) {
        float s = 0.f;
        #pragma unroll
        for (int ww = 0; ww < 8; ww++) s += part[ww][idx];
        logits[idx] = s;
    }
    __syncthreads();

    if (tid < 8) {
        const float* lg = logits + tid * 65;
        int t = t0 + tid;
        unsigned long long used = 0ull;
        float vals[TOPK]; int idx[TOPK];
        for (int k = 0; k < TOPK; k++) {
            float best = -INFINITY; int bi = 0;
            for (int e = 0; e < E_NUM; e++)
                if (!((used >> e) & 1ull) && lg[e] > best) { best = lg[e]; bi = e; }
            used |= 1ull << bi; vals[k] = best; idx[k] = bi;
        }
        float m = vals[0], sum = 0.f, wgt[TOPK];
        for (int k = 0; k < TOPK; k++) { wgt[k] = expf(vals[k] - m); sum += wgt[k]; }
        float inv = 1.f / sum;
        for (int k = 0; k < TOPK; k++) {
            d_topk_w[t * TOPK + k]  = wgt[k] * inv;
            d_topk_idx[t * TOPK + k] = idx[k];
        }
        d_sgate[t] = lg[E_NUM];
    }
}

// ------- dispatch v2: single block, match_any + cross-warp scan, stable ranks -------
__global__ void __launch_bounds__(1024)
dispatch_kernel() {
    __shared__ int wcnt[32][64];
    __shared__ int woff[32][64];
    __shared__ int base[64];

    int tid = threadIdx.x, w = tid >> 5, lane = tid & 31;
    if (tid < 64) base[tid] = 0;
    int myrun = 0;

    for (int r = 0; r < 8; r++) {
        int i = r * 1024 + tid;
        int e = d_topk_idx[i];
        unsigned mask = __match_any_sync(0xffffffffu, e);
        int lr = __popc(mask & ((1u << lane) - 1u));
        bool leader = ((__ffs(mask) - 1) == lane);

        ((int*)wcnt)[tid * 2]     = 0;
        ((int*)wcnt)[tid * 2 + 1] = 0;
        __syncthreads();
        if (leader) wcnt[w][e] = __popc(mask);
        __syncthreads();
        if (tid < 64) {
            int run = 0;
            #pragma unroll
            for (int ww = 0; ww < 32; ww++) { woff[ww][tid] = run; run += wcnt[ww][tid]; }
            myrun = run;
        }
        __syncthreads();
        int pos = base[e] + woff[w][e] + lr;
        d_pos[i] = pos;
        if (pos < CAP) d_toklist[e * CAP + pos] = i >> 3;
        __syncthreads();
        if (tid < 64) base[tid] += myrun;
        __syncthreads();
    }
    if (tid < 64) d_cnt[tid] = min(base[tid], CAP);
}

// ---------------- dual GEMM fp16 (C1=A@B1, C3=A@B3) + SwiGLU epilogue ----------------
// 256 threads, 8 warps (4m x 2n), block tile 128x64 per mat, warp tile 32x32.
// smem: A [m][k2] half2 (pad 20), B [k2][n] half2 (pad 72). fp32 accumulate.
__global__ void __launch_bounds__(256, 2)
dual_gemm_silu(const float* __restrict__ A, int lda, size_t strideA,
               const int* __restrict__ gather, const int* __restrict__ cnt,
               int mfull, int mtiles,
               const float* __restrict__ B1g, const float* __restrict__ B3g,
               int ldb, size_t strideB,
               float* __restrict__ Out, int ldo, size_t strideOut, int K) {
    extern __shared__ unsigned smu[];
    unsigned* As2  = smu;                     // 2 * 2560
    unsigned* B1s2 = smu + 2 * A_STG;         // 2 * 1152
    unsigned* B3s2 = B1s2 + 2 * BD_STG;       // 2 * 1152

    int e = blockIdx.x / mtiles;
    int mt = blockIdx.x - e * mtiles;
    int noff = blockIdx.y * 64;
    int nrows = cnt ? (cnt[e] - mt * 128) : (mfull - mt * 128);
    if (nrows <= 0) return;
    int valid = min(128, nrows);

    int tid = threadIdx.x;

    // A producer: 4 rows/thread, 4 floats each
    const float* ap[4]; int asoff[4];
    {
        int c4 = (tid & 7) * 4, arow0 = tid >> 3;
        #pragma unroll
        for (int i = 0; i < 4; i++) {
            int r = arow0 + i * 32;
            int rr = min(r, valid - 1);
            long grow = gather ? (long)gather[e * CAP + mt * 128 + rr] : ((long)mt * 128 + rr);
            ap[i] = A + (size_t)e * strideA + (size_t)grow * lda + c4;
            asoff[i] = r * ASTRH + (tid & 7) * 2;
        }
    }
    // B producer: one (k2, n4) slot per thread per mat; loads rows 2k2, 2k2+1
    const float *b1p, *b3p; int bsoff;
    {
        int k2 = tid >> 4, n4 = (tid & 15) * 4;
        size_t go = (size_t)e * strideB + (size_t)(2 * k2) * ldb + noff + n4;
        b1p = B1g + go; b3p = B3g + go;
        bsoff = k2 * BSTRH_D + n4;
    }

    float c1[2][4][4], c3[2][4][4];
    #pragma unroll
    for (int a = 0; a < 2; a++)
        #pragma unroll
        for (int b = 0; b < 4; b++)
            #pragma unroll
            for (int r = 0; r < 4; r++) { c1[a][b][r] = 0.f; c3[a][b][r] = 0.f; }

    int warp = tid >> 5, lane = tid & 31;
    int wm = warp & 3, wn = warp >> 2;
    int g = lane >> 2, t4 = lane & 3;

    uint2 raA[4];
    uint4 rb1, rb3;
    auto ldg_all = [&]() {
        #pragma unroll
        for (int i = 0; i < 4; i++) {
            float4 v = *(const float4*)ap[i]; ap[i] += BKx;
            raA[i] = make_uint2(pack2(v.x, v.y), pack2(v.z, v.w));
        }
        float4 lo1 = *(const float4*)b1p, hi1 = *(const float4*)(b1p + ldb);
        b1p += (size_t)BKx * ldb;
        rb1 = make_uint4(pack2(lo1.x, hi1.x), pack2(lo1.y, hi1.y),
                         pack2(lo1.z, hi1.z), pack2(lo1.w, hi1.w));
        float4 lo3 = *(const float4*)b3p, hi3 = *(const float4*)(b3p + ldb);
        b3p += (size_t)BKx * ldb;
        rb3 = make_uint4(pack2(lo3.x, hi3.x), pack2(lo3.y, hi3.y),
                         pack2(lo3.z, hi3.z), pack2(lo3.w, hi3.w));
    };
    auto sts_all = [&](int s) {
        #pragma unroll
        for (int i = 0; i < 4; i++)
            *(uint2*)&As2[s * A_STG + asoff[i]] = raA[i];
        *(uint4*)&B1s2[s * BD_STG + bsoff] = rb1;
        *(uint4*)&B3s2[s * BD_STG + bsoff] = rb3;
    };

    int nk = K / BKx;
    ldg_all();
    for (int i = 0; i < nk; i++) {
        int s = i & 1;
        sts_all(s);
        __syncthreads();
        if (i + 1 < nk) ldg_all();
        const unsigned* as  = As2 + s * A_STG;
        const unsigned* b1s = B1s2 + s * BD_STG;
        const unsigned* b3s = B3s2 + s * BD_STG;
        #pragma unroll
        for (int kk2 = 0; kk2 < 2; kk2++) {
            int kb = kk2 * 8 + t4;
            unsigned af[2][4];
            #pragma unroll
            for (int mf = 0; mf < 2; mf++) {
                int r0 = wm * 32 + mf * 16 + g;
                af[mf][0] = as[r0 * ASTRH + kb];
                af[mf][1] = as[(r0 + 8) * ASTRH + kb];
                af[mf][2] = as[r0 * ASTRH + kb + 4];
                af[mf][3] = as[(r0 + 8) * ASTRH + kb + 4];
            }
            unsigned bf1[4][2], bf3[4][2];
            #pragma unroll
            for (int nf = 0; nf < 4; nf++) {
                int cn = wn * 32 + nf * 8 + g;
                bf1[nf][0] = b1s[kb * BSTRH_D + cn];
                bf1[nf][1] = b1s[(kb + 4) * BSTRH_D + cn];
                bf3[nf][0] = b3s[kb * BSTRH_D + cn];
                bf3[nf][1] = b3s[(kb + 4) * BSTRH_D + cn];
            }
            #pragma unroll
            for (int mf = 0; mf < 2; mf++)
                #pragma unroll
                for (int nf = 0; nf < 4; nf++) {
                    mma16(c1[mf][nf], af[mf], bf1[nf][0], bf1[nf][1]);
                    mma16(c3[mf][nf], af[mf], bf3[nf][0], bf3[nf][1]);
                }
        }
        __syncthreads();
    }

    float* outp = Out + (size_t)e * strideOut + (size_t)mt * 128 * ldo + noff;
    #pragma unroll
    for (int mf = 0; mf < 2; mf++)
        #pragma unroll
        for (int nf = 0; nf < 4; nf++) {
            int r0 = wm * 32 + mf * 16 + g;
            int cc = wn * 32 + nf * 8 + t4 * 2;
            #pragma unroll
            for (int h = 0; h < 2; h++) {
                int r = r0 + h * 8;
                if (r < valid) {
                    float v1a = c1[mf][nf][h * 2 + 0], v3a = c3[mf][nf][h * 2 + 0];
                    float v1b = c1[mf][nf][h * 2 + 1], v3b = c3[mf][nf][h * 2 + 1];
                    float ga = (v1a / (1.f + expf(-v1a))) * v3a;
                    float gb = (v1b / (1.f + expf(-v1b))) * v3b;
                    *(float2*)(outp + (size_t)r * ldo + cc) = make_float2(ga, gb);
                }
            }
        }
}

// ---------------- single GEMM fp16 (C = A @ B) ----------------
// 256 threads, 8 warps (4m x 2n), block tile 128x128, warp tile 32x64.
__global__ void __launch_bounds__(256, 2)
single_gemm(const float* __restrict__ A, int lda, size_t strideA,
            const int* __restrict__ cnt, int mfull, int mtiles,
            const float* __restrict__ Bg, int ldb, size_t strideB,
            float* __restrict__ Out, int ldo, size_t strideOut, int K) {
    extern __shared__ unsigned smu[];
    unsigned* As2 = smu;                  // 2 * 2560
    unsigned* Bs2 = smu + 2 * A_STG;      // 2 * 2176

    int e = blockIdx.x / mtiles;
    int mt = blockIdx.x - e * mtiles;
    int noff = blockIdx.y * 128;
    int nrows = cnt ? (cnt[e] - mt * 128) : (mfull - mt * 128);
    if (nrows <= 0) return;
    int valid = min(128, nrows);

    int tid = threadIdx.x;

    const float* ap[4]; int asoff[4];
    {
        int c4 = (tid & 7) * 4, arow0 = tid >> 3;
        #pragma unroll
        for (int i = 0; i < 4; i++) {
            int r = arow0 + i * 32;
            int rr = min(r, valid - 1);
            ap[i] = A + (size_t)e * strideA + ((size_t)mt * 128 + rr) * lda + c4;
            asoff[i] = r * ASTRH + (tid & 7) * 2;
        }
    }
    const float* bp[2]; int bsoff[2];
    #pragma unroll
    for (int j = 0; j < 2; j++) {
        int slot = tid + j * 256;
        int k2 = slot >> 5, n4 = (slot & 31) * 4;
        bp[j] = Bg + (size_t)e * strideB + (size_t)(2 * k2) * ldb + noff + n4;
        bsoff[j] = k2 * BSTRH_S + n4;
    }

    float c[2][8][4];
    #pragma unroll
    for (int a = 0; a < 2; a++)
        #pragma unroll
        for (int b = 0; b < 8; b++)
            #pragma unroll
            for (int r = 0; r < 4; r++) c[a][b][r] = 0.f;

    int warp = tid >> 5, lane = tid & 31;
    int wm = warp & 3, wn = warp >> 2;
    int g = lane >> 2, t4 = lane & 3;

    uint2 raA[4];
    uint4 rbS[2];
    auto ldg_all = [&]() {
        #pragma unroll
        for (int i = 0; i < 4; i++) {
            float4 v = *(const float4*)ap[i]; ap[i] += BKx;
            raA[i] = make_uint2(pack2(v.x, v.y), pack2(v.z, v.w));
        }
        #pragma unroll
        for (int j = 0; j < 2; j++) {
            float4 lo = *(const float4*)bp[j], hi = *(const float4*)(bp[j] + ldb);
            bp[j] += (size_t)BKx * ldb;
            rbS[j] = make_uint4(pack2(lo.x, hi.x), pack2(lo.y, hi.y),
                                pack2(lo.z, hi.z), pack2(lo.w, hi.w));
        }
    };
    auto sts_all = [&](int s) {
        #pragma unroll
        for (int i = 0; i < 4; i++)
            *(uint2*)&As2[s * A_STG + asoff[i]] = raA[i];
        #pragma unroll
        for (int j = 0; j < 2; j++)
            *(uint4*)&Bs2[s * BS_STG + bsoff[j]] = rbS[j];
    };

    int nk = K / BKx;
    ldg_all();
    for (int i = 0; i < nk; i++) {
        int s = i & 1;
        sts_all(s);
        __syncthreads();
        if (i + 1 < nk) ldg_all();
        const unsigned* as = As2 + s * A_STG;
        const unsigned* bs = Bs2 + s * BS_STG;
        #pragma unroll
        for (int kk2 = 0; kk2 < 2; kk2++) {
            int kb = kk2 * 8 + t4;
            unsigned af[2][4];
            #pragma unroll
            for (int mf = 0; mf < 2; mf++) {
                int r0 = wm * 32 + mf * 16 + g;
                af[mf][0] = as[r0 * ASTRH + kb];
                af[mf][1] = as[(r0 + 8) * ASTRH + kb];
                af[mf][2] = as[r0 * ASTRH + kb + 4];
                af[mf][3] = as[(r0 + 8) * ASTRH + kb + 4];
            }
            unsigned bf[8][2];
            #pragma unroll
            for (int nf = 0; nf < 8; nf++) {
                int cn = wn * 64 + nf * 8 + g;
                bf[nf][0] = bs[kb * BSTRH_S + cn];
                bf[nf][1] = bs[(kb + 4) * BSTRH_S + cn];
            }
            #pragma unroll
            for (int mf = 0; mf < 2; mf++)
                #pragma unroll
                for (int nf = 0; nf < 8; nf++)
                    mma16(c[mf][nf], af[mf], bf[nf][0], bf[nf][1]);
        }
        __syncthreads();
    }

    float* outp = Out + (size_t)e * strideOut + (size_t)mt * 128 * ldo + noff;
    #pragma unroll
    for (int mf = 0; mf < 2; mf++)
        #pragma unroll
        for (int nf = 0; nf < 8; nf++) {
            int r0 = wm * 32 + mf * 16 + g;
            int cc = wn * 64 + nf * 8 + t4 * 2;
            #pragma unroll
            for (int h = 0; h < 2; h++) {
                int r = r0 + h * 8;
                if (r < valid)
                    *(float2*)(outp + (size_t)r * ldo + cc) =
                        make_float2(c[mf][nf][h * 2 + 0], c[mf][nf][h * 2 + 1]);
            }
        }
}

// ---------------- combine: routed + sigmoid-gated shared ----------------
__global__ void combine_kernel(float* __restrict__ out) {
    int t = blockIdx.x;
    __shared__ int rows[TOPK];
    __shared__ float ws[TOPK];
    if (threadIdx.x < TOPK) {
        int k = threadIdx.x;
        int ee = d_topk_idx[t * TOPK + k];
        int p  = d_pos[t * TOPK + k];
        rows[k] = (p < CAP) ? (ee * CAP + p) : -1;
        ws[k] = d_topk_w[t * TOPK + k];
    }
    __syncthreads();
    float sg = 1.f / (1.f + expf(-d_sgate[t]));
    #pragma unroll
    for (int j = 0; j < 2; j++) {
        int h = threadIdx.x * 4 + j * 1024;
        float4 acc = *(const float4*)(d_s2 + (size_t)t * H_DIM + h);
        acc.x *= sg; acc.y *= sg; acc.z *= sg; acc.w *= sg;
        #pragma unroll
        for (int k = 0; k < TOPK; k++) {
            int r = rows[k];
            if (r >= 0) {
                float w = ws[k];
                float4 y = *(const float4*)(d_yb + (size_t)r * H_DIM + h);
                acc.x += w * y.x; acc.y += w * y.y; acc.z += w * y.z; acc.w += w * y.w;
            }
        }
        *(float4*)(out + (size_t)t * H_DIM + h) = acc;
    }
}

// ---------------- launch ----------------
extern "C" void kernel_launch(void* const* d_in, const int* in_sizes, int n_in,
                              void* d_out, int out_size) {
    (void)in_sizes; (void)n_in; (void)out_size;
    const float* x   = (const float*)d_in[0];
    const float* gw  = (const float*)d_in[1];
    const float* w1  = (const float*)d_in[2];
    const float* w3  = (const float*)d_in[3];
    const float* w2  = (const float*)d_in[4];
    const float* ws1 = (const float*)d_in[5];
    const float* ws3 = (const float*)d_in[6];
    const float* ws2 = (const float*)d_in[7];
    const float* wsg = (const float*)d_in[8];
    float* out = (float*)d_out;

    static cudaStream_t sB = nullptr;
    static cudaEvent_t evFork = nullptr, evJoin = nullptr;
    if (sB == nullptr) {
        cudaStreamCreateWithFlags(&sB, cudaStreamNonBlocking);
        cudaEventCreateWithFlags(&evFork, cudaEventDisableTiming);
        cudaEventCreateWithFlags(&evJoin, cudaEventDisableTiming);
    }

    cudaFuncSetAttribute(dual_gemm_silu, cudaFuncAttributeMaxDynamicSharedMemorySize, SMEM_DUAL);
    cudaFuncSetAttribute(single_gemm,    cudaFuncAttributeMaxDynamicSharedMemorySize, SMEM_SINGLE);

    float *gbuf, *yb, *s1, *s2;
    int *cnt, *toklist;
    cudaGetSymbolAddress((void**)&gbuf, d_gbuf);
    cudaGetSymbolAddress((void**)&yb, d_yb);
    cudaGetSymbolAddress((void**)&s1, d_s1);
    cudaGetSymbolAddress((void**)&s2, d_s2);
    cudaGetSymbolAddress((void**)&cnt, d_cnt);
    cudaGetSymbolAddress((void**)&toklist, d_toklist);

    // fork: shared-expert chain is independent of router/dispatch/experts
    cudaEventRecord(evFork, 0);
    cudaStreamWaitEvent(sB, evFork, 0);

    // ---- stream B: shared expert chain ----
    dual_gemm_silu<<<dim3(8, IS_DIM / 64), 256, SMEM_DUAL, sB>>>(
        x, H_DIM, 0, nullptr, nullptr, T_TOK, 8,
        ws1, ws3, IS_DIM, 0,
        s1, IS_DIM, 0, H_DIM);
    single_gemm<<<dim3(8, H_DIM / 128), 256, SMEM_SINGLE, sB>>>(
        s1, IS_DIM, 0, nullptr, T_TOK, 8,
        ws2, H_DIM, 0,
        s2, H_DIM, 0, IS_DIM);
    cudaEventRecord(evJoin, sB);

    // ---- default stream: routed expert chain ----
    router_kernel<<<T_TOK / 8, 256>>>(x, gw, wsg);
    dispatch_kernel<<<1, 1024>>>();

    dual_gemm_silu<<<dim3(E_NUM * 2, I_DIM / 64), 256, SMEM_DUAL>>>(
        x, H_DIM, 0, toklist, cnt, 0, 2,
        w1, w3, I_DIM, (size_t)H_DIM * I_DIM,
        gbuf, I_DIM, (size_t)CAP * I_DIM, H_DIM);

    single_gemm<<<dim3(E_NUM * 2, H_DIM / 128), 256, SMEM_SINGLE>>>(
        gbuf, I_DIM, (size_t)CAP * I_DIM, cnt, 0, 2,
        w2, H_DIM, (size_t)I_DIM * H_DIM,
        yb, H_DIM, (size_t)CAP * H_DIM, I_DIM);

    // join: combine needs both chains
    cudaStreamWaitEvent(0, evJoin, 0);
    combine_kernel<<<T_TOK, 256>>>(out);
}